// round 1
// baseline (speedup 1.0000x reference)
#include <cuda_runtime.h>
#include <math.h>

// Problem constants
#define CB 4
#define CL 2048
#define CH 512
#define CN 8
#define CD 64
#define CBL (CB*CL)   // 8192

// ---------------- scratch (device globals; no allocations allowed) ----------
__device__ float g_Wqkv[CH*3*CH];     // [h][which*512 + n*64 + d]
__device__ float g_WrP [CH*CH];       // [h][n*64+d]
__device__ float g_WcT [CH*CH];       // [k][j] = Wc[j][k]
__device__ float g_W1T [CH*CH];
__device__ float g_W2T [CH*CH];
__device__ float g_qc  [CB*CN*CL*CD]; // q + bq + content_bias
__device__ float g_k   [CB*CN*CL*CD];
__device__ float g_v   [CB*CN*CL*CD];
__device__ float g_r   [CN*CL*CD];
__device__ float g_att [CBL*CH];
__device__ float g_t1  [CBL*CH];
__device__ float g_a   [CBL*CH];
__device__ float g_h1  [CBL*CH];
__device__ float g_t2  [CBL*CH];

// ---------------- weight repack ----------------
__global__ void pack_kernel(const float* __restrict__ Wq, const float* __restrict__ Wk,
                            const float* __restrict__ Wv, const float* __restrict__ Wr,
                            const float* __restrict__ Wc, const float* __restrict__ W1,
                            const float* __restrict__ W2)
{
    int idx = blockIdx.x*blockDim.x + threadIdx.x;
    int stride = gridDim.x*blockDim.x;
    // Wqkv: [512][1536]
    for (int i = idx; i < CH*3*CH; i += stride) {
        int h = i / (3*CH);
        int j = i % (3*CH);
        int which = j >> 9;           // /512
        int rr = j & 511;
        int n = rr >> 6, d = rr & 63;
        const float* W = (which==0) ? Wq : (which==1) ? Wk : Wv;
        g_Wqkv[i] = W[(n*CH + h)*CD + d];
    }
    for (int i = idx; i < CH*CH; i += stride) {
        int h = i / CH, j = i % CH;
        int n = j >> 6, d = j & 63;
        g_WrP[i] = Wr[(n*CH + h)*CD + d];
        g_WcT[i] = Wc[j*CH + h];
        g_W1T[i] = W1[j*CH + h];
        g_W2T[i] = W2[j*CH + h];
    }
}

// ---------------- generic 128x128x8 SGEMM with fused epilogues --------------
// EPI: 0 = QKV split-write, 1 = R write, 2 = +bias store, 3 = +bias gelu store
template<int EPI>
__global__ void __launch_bounds__(256) sgemm(const float* __restrict__ A,
    const float* __restrict__ Bm, int M, int Nc, int K,
    const float* __restrict__ aux0, const float* __restrict__ aux1,
    const float* __restrict__ aux2, const float* __restrict__ aux3,
    float* __restrict__ out0)
{
    __shared__ float As[8][128];
    __shared__ float Bs[8][128];
    const int t  = threadIdx.x;
    const int bm = blockIdx.y * 128, bn = blockIdx.x * 128;
    const int arow = t >> 1, acol = (t & 1) * 4;
    const int brow = t >> 5, bcol = (t & 31) * 4;
    const int tx = t & 15, ty = t >> 4;

    float acc[8][8];
#pragma unroll
    for (int i=0;i<8;i++)
#pragma unroll
        for (int j=0;j<8;j++) acc[i][j]=0.f;

    const float* Aptr = A + (size_t)(bm + arow)*K + acol;
    const float* Bptr = Bm + (size_t)brow*Nc + bn + bcol;

    for (int k0 = 0; k0 < K; k0 += 8) {
        float4 av = *(const float4*)(Aptr + k0);
        As[acol+0][arow]=av.x; As[acol+1][arow]=av.y;
        As[acol+2][arow]=av.z; As[acol+3][arow]=av.w;
        float4 bv = *(const float4*)(Bptr + (size_t)k0*Nc);
        *(float4*)&Bs[brow][bcol] = bv;
        __syncthreads();
#pragma unroll
        for (int kk=0; kk<8; kk++) {
            float ar[8], br_[8];
            *(float4*)(ar)    = *(const float4*)&As[kk][ty*8];
            *(float4*)(ar+4)  = *(const float4*)&As[kk][ty*8+4];
            *(float4*)(br_)   = *(const float4*)&Bs[kk][tx*8];
            *(float4*)(br_+4) = *(const float4*)&Bs[kk][tx*8+4];
#pragma unroll
            for (int i=0;i<8;i++)
#pragma unroll
                for (int j=0;j<8;j++)
                    acc[i][j] = fmaf(ar[i], br_[j], acc[i][j]);
        }
        __syncthreads();
    }

#pragma unroll
    for (int i=0;i<8;i++) {
        int row = bm + ty*8 + i;
#pragma unroll
        for (int j=0;j<8;j++) {
            int col = bn + tx*8 + j;
            float val = acc[i][j];
            if (EPI == 0) {            // QKV -> g_qc / g_k / g_v in [b][n][l][d]
                int b = row >> 11, l = row & 2047;
                int which = col >> 9, rr = col & 511;
                int n = rr >> 6, d = rr & 63;
                int dst = ((b*CN + n)*CL + l)*CD + d;
                if (which == 0)      g_qc[dst] = val + aux0[rr] + aux3[rr];
                else if (which == 1) g_k[dst]  = val + aux1[rr];
                else                 g_v[dst]  = val + aux2[rr];
            } else if (EPI == 1) {     // R -> g_r [n][p][d]
                int n = col >> 6, d = col & 63;
                g_r[(n*CL + row)*CD + d] = val + aux0[col];
            } else if (EPI == 2) {     // +bias
                out0[(size_t)row*Nc + col] = val + aux0[col];
            } else {                   // gelu(+bias)
                float v2 = val + aux0[col];
                out0[(size_t)row*Nc + col] =
                    0.5f*v2*(1.0f + erff(v2*0.70710678118654752f));
            }
        }
    }
}

// ---------------- fast exp on FMA pipe (avoid MUFU bottleneck) --------------
__device__ __forceinline__ float fexp(float x) {
    float tt = fmaxf(x * 1.4426950408889634f, -126.0f);
    float fi = floorf(tt);
    float f  = tt - fi;
    float p  = 1.5403530393381609e-4f;
    p = fmaf(p, f, 1.3333558146428443e-3f);
    p = fmaf(p, f, 9.6181291076284772e-3f);
    p = fmaf(p, f, 5.5504108664821580e-2f);
    p = fmaf(p, f, 2.4022650695910072e-1f);
    p = fmaf(p, f, 6.9314718055994531e-1f);
    p = fmaf(p, f, 1.0f);
    return p * __int_as_float(((int)fi + 127) << 23);
}

__device__ __forceinline__ float rmax16(float v) {
#pragma unroll
    for (int m=1;m<16;m<<=1) v = fmaxf(v, __shfl_xor_sync(0xffffffffu, v, m));
    return v;
}
__device__ __forceinline__ float rsum16(float v) {
#pragma unroll
    for (int m=1;m<16;m<<=1) v += __shfl_xor_sync(0xffffffffu, v, m);
    return v;
}

// ---------------- fused causal flash attention with rel-shift ---------------
// scores[i,j] = (qc_i . k_j + qp_i . r[L-1-(i-j)]) / 8   for j <= i
// qp = qc + delta, delta = pos_bias - content_bias
// smem (floats): qcT 4096 | kT/P 4096 | V 4096 | rT 8192 | delta 64
#define ATTN_SMEM_FLOATS (4096*3 + 8192 + 64)
__global__ void __launch_bounds__(256) attn_kernel(const float* __restrict__ cbias,
                                                   const float* __restrict__ pbias)
{
    extern __shared__ float sm[];
    float* qcT = sm;               // [d][row]   d-major
    float* kTs = sm + 4096;        // [d][col]   (aliased by P [row][col] later)
    float* Vs  = sm + 8192;        // [row][d]
    float* rTs = sm + 12288;       // [d][t], t in [0,128)
    float* dlt = sm + 20480;       // [64]

    const int t  = threadIdx.x;
    const int tx = t & 15, ty = t >> 4;
    const int r0 = ty*4, c0 = tx*4;
    const int it = blockIdx.x, n = blockIdx.y, b = blockIdx.z;
    const int i0 = it * 64;
    const int bn_base = (b*CN + n)*CL;

    // loader indices
    const int d4 = (t & 15)*4;
    const int rb = t >> 4;  // 0..15

    // load qcT (transpose) + delta
#pragma unroll
    for (int ii=0; ii<4; ii++) {
        int row = rb + ii*16;
        float4 qv = *(const float4*)&g_qc[(bn_base + i0 + row)*CD + d4];
        qcT[(d4+0)*64+row]=qv.x; qcT[(d4+1)*64+row]=qv.y;
        qcT[(d4+2)*64+row]=qv.z; qcT[(d4+3)*64+row]=qv.w;
    }
    if (t < 64) dlt[t] = pbias[n*CD + t] - cbias[n*CD + t];
    __syncthreads();

    float m_[4], l_[4], O[4][4];
#pragma unroll
    for (int a=0;a<4;a++){ m_[a]=-1e30f; l_[a]=0.f;
#pragma unroll
        for (int c=0;c<4;c++) O[a][c]=0.f; }

    const int rbase = 60 - r0 + c0;  // float4-aligned base into r slab

    for (int j0 = 0; j0 <= i0; j0 += 64) {
        __syncthreads();   // protect P/V/r from previous iteration
        // load kT (transpose)
#pragma unroll
        for (int ii=0; ii<4; ii++) {
            int row = rb + ii*16;
            float4 kv = *(const float4*)&g_k[(bn_base + j0 + row)*CD + d4];
            kTs[(d4+0)*64+row]=kv.x; kTs[(d4+1)*64+row]=kv.y;
            kTs[(d4+2)*64+row]=kv.z; kTs[(d4+3)*64+row]=kv.w;
        }
        // load V (natural)
#pragma unroll
        for (int ii=0; ii<4; ii++) {
            int e = t + ii*256;          // float4 unit
            int row = e >> 4, cc4 = (e & 15)*4;
            *(float4*)&Vs[row*64 + cc4] =
                *(const float4*)&g_v[(bn_base + j0 + row)*CD + cc4];
        }
        // load r slab (transpose), rows p = pbase + [0,128)
        {
            int pbase = CL - 64 - i0 + j0;
#pragma unroll
            for (int ii=0; ii<8; ii++) {
                int trow = rb + ii*16;
                int p = pbase + trow;
                float4 rv4 = make_float4(0.f,0.f,0.f,0.f);
                if (p < CL) rv4 = *(const float4*)&g_r[(n*CL + p)*CD + d4];
                rTs[(d4+0)*128+trow]=rv4.x; rTs[(d4+1)*128+trow]=rv4.y;
                rTs[(d4+2)*128+trow]=rv4.z; rTs[(d4+3)*128+trow]=rv4.w;
            }
        }
        __syncthreads();

        // S = qc.K^T + qp.r_shift
        float S[4][4];
#pragma unroll
        for (int a=0;a<4;a++)
#pragma unroll
            for (int c=0;c<4;c++) S[a][c]=0.f;

#pragma unroll 4
        for (int kk=0; kk<64; kk++) {
            float d_ = dlt[kk];
            float4 q4 = *(const float4*)&qcT[kk*64 + r0];
            float4 k4 = *(const float4*)&kTs[kk*64 + c0];
            float4 rA = *(const float4*)&rTs[kk*128 + rbase];
            float4 rB = *(const float4*)&rTs[kk*128 + rbase + 4];
            float qv[4] = {q4.x,q4.y,q4.z,q4.w};
            float kv[4] = {k4.x,k4.y,k4.z,k4.w};
            float rv[8] = {rA.x,rA.y,rA.z,rA.w,rB.x,rB.y,rB.z,rB.w};
            float qp[4];
#pragma unroll
            for (int a=0;a<4;a++) qp[a] = qv[a] + d_;
#pragma unroll
            for (int a=0;a<4;a++)
#pragma unroll
                for (int c=0;c<4;c++)
                    S[a][c] = fmaf(qv[a], kv[c],
                               fmaf(qp[a], rv[3 - a + c], S[a][c]));
        }

        // scale + (diag-tile) mask
#pragma unroll
        for (int a=0;a<4;a++)
#pragma unroll
            for (int c=0;c<4;c++) S[a][c] *= 0.125f;
        if (j0 == i0) {
#pragma unroll
            for (int a=0;a<4;a++)
#pragma unroll
                for (int c=0;c<4;c++)
                    if (c0 + c > r0 + a) S[a][c] = -1e30f;
        }

        // online softmax update
        float P[4][4];
#pragma unroll
        for (int a=0;a<4;a++) {
            float rm = fmaxf(fmaxf(S[a][0],S[a][1]), fmaxf(S[a][2],S[a][3]));
            rm = rmax16(rm);
            float mn = fmaxf(m_[a], rm);
            float corr = fexp(m_[a] - mn);
            m_[a] = mn;
            float rs = 0.f;
#pragma unroll
            for (int c=0;c<4;c++){ P[a][c] = fexp(S[a][c]-mn); rs += P[a][c]; }
            rs = rsum16(rs);
            l_[a] = l_[a]*corr + rs;
#pragma unroll
            for (int c=0;c<4;c++) O[a][c] *= corr;
        }

        __syncthreads();   // all warps done reading kTs
        float* Ps = kTs;   // alias
#pragma unroll
        for (int a=0;a<4;a++)
            *(float4*)&Ps[(r0+a)*64 + c0] =
                make_float4(P[a][0],P[a][1],P[a][2],P[a][3]);
        __syncthreads();

        // O += P @ V
#pragma unroll 4
        for (int nj=0; nj<64; nj++) {
            float4 v4 = *(const float4*)&Vs[nj*64 + c0];
            float vv[4] = {v4.x,v4.y,v4.z,v4.w};
            float p0 = Ps[(r0+0)*64+nj], p1 = Ps[(r0+1)*64+nj];
            float p2 = Ps[(r0+2)*64+nj], p3 = Ps[(r0+3)*64+nj];
#pragma unroll
            for (int c=0;c<4;c++) {
                O[0][c] = fmaf(p0, vv[c], O[0][c]);
                O[1][c] = fmaf(p1, vv[c], O[1][c]);
                O[2][c] = fmaf(p2, vv[c], O[2][c]);
                O[3][c] = fmaf(p3, vv[c], O[3][c]);
            }
        }
    }

    // normalize + write [b][l][n*64+d]
#pragma unroll
    for (int a=0;a<4;a++) {
        float inv = 1.0f / l_[a];
        float4 o4 = make_float4(O[a][0]*inv, O[a][1]*inv, O[a][2]*inv, O[a][3]*inv);
        *(float4*)&g_att[(size_t)(b*CL + i0 + r0 + a)*CH + n*CD + c0] = o4;
    }
}

// ---------------- layernorm(X + R) --------------------------------------
__global__ void __launch_bounds__(256) ln_kernel(const float* __restrict__ X,
    const float* __restrict__ R, const float* __restrict__ w,
    const float* __restrict__ bb, float* __restrict__ out)
{
    __shared__ float sh[8];
    int row = blockIdx.x, t = threadIdx.x;
    const float* xp = X + (size_t)row*CH;
    const float* rp = R + (size_t)row*CH;
    float v0 = xp[t] + rp[t];
    float v1 = xp[t+256] + rp[t+256];

    float s = v0 + v1;
#pragma unroll
    for (int m=16;m;m>>=1) s += __shfl_xor_sync(0xffffffffu, s, m);
    if ((t & 31)==0) sh[t>>5] = s;
    __syncthreads();
    float tot = 0.f;
#pragma unroll
    for (int i=0;i<8;i++) tot += sh[i];
    __syncthreads();
    float mean = tot * (1.0f/CH);
    float d0 = v0 - mean, d1 = v1 - mean;
    float s2 = d0*d0 + d1*d1;
#pragma unroll
    for (int m=16;m;m>>=1) s2 += __shfl_xor_sync(0xffffffffu, s2, m);
    if ((t & 31)==0) sh[t>>5] = s2;
    __syncthreads();
    float tot2 = 0.f;
#pragma unroll
    for (int i=0;i<8;i++) tot2 += sh[i];
    float rstd = rsqrtf(tot2*(1.0f/CH) + 1e-12f);
    out[(size_t)row*CH + t]       = w[t]*d0*rstd + bb[t];
    out[(size_t)row*CH + t + 256] = w[t+256]*d1*rstd + bb[t+256];
}

// ---------------- launch ----------------------------------------------------
extern "C" void kernel_launch(void* const* d_in, const int* in_sizes, int n_in,
                              void* d_out, int out_size)
{
    const float* x   = (const float*)d_in[0];
    const float* pe  = (const float*)d_in[1];
    const float* Wq  = (const float*)d_in[2];
    const float* bq  = (const float*)d_in[3];
    const float* Wk  = (const float*)d_in[4];
    const float* bk  = (const float*)d_in[5];
    const float* Wv  = (const float*)d_in[6];
    const float* bv  = (const float*)d_in[7];
    const float* Wr  = (const float*)d_in[8];
    const float* br  = (const float*)d_in[9];
    const float* cbv = (const float*)d_in[10];
    const float* pbv = (const float*)d_in[11];
    const float* Wc  = (const float*)d_in[12];
    const float* bc  = (const float*)d_in[13];
    const float* W1  = (const float*)d_in[14];
    const float* b1  = (const float*)d_in[15];
    const float* W2  = (const float*)d_in[16];
    const float* b2  = (const float*)d_in[17];
    const float* lnw = (const float*)d_in[18];
    const float* lnb = (const float*)d_in[19];
    float* out = (float*)d_out;

    float *pWqkv, *pWrP, *pWcT, *pW1T, *pW2T, *pAtt, *pT1, *pA, *pH1, *pT2;
    cudaGetSymbolAddress((void**)&pWqkv, g_Wqkv);
    cudaGetSymbolAddress((void**)&pWrP,  g_WrP);
    cudaGetSymbolAddress((void**)&pWcT,  g_WcT);
    cudaGetSymbolAddress((void**)&pW1T,  g_W1T);
    cudaGetSymbolAddress((void**)&pW2T,  g_W2T);
    cudaGetSymbolAddress((void**)&pAtt,  g_att);
    cudaGetSymbolAddress((void**)&pT1,   g_t1);
    cudaGetSymbolAddress((void**)&pA,    g_a);
    cudaGetSymbolAddress((void**)&pH1,   g_h1);
    cudaGetSymbolAddress((void**)&pT2,   g_t2);

    const int attn_smem = ATTN_SMEM_FLOATS * 4;
    cudaFuncSetAttribute(attn_kernel,
        cudaFuncAttributeMaxDynamicSharedMemorySize, attn_smem);

    pack_kernel<<<128, 256>>>(Wq, Wk, Wv, Wr, Wc, W1, W2);

    // QKV: [8192,512] x [512,1536]
    sgemm<0><<<dim3(1536/128, CBL/128), 256>>>(x, pWqkv, CBL, 1536, CH,
                                               bq, bk, bv, cbv, nullptr);
    // R: [2048,512] x [512,512]
    sgemm<1><<<dim3(CH/128, CL/128), 256>>>(pe, pWrP, CL, CH, CH,
                                            br, nullptr, nullptr, nullptr, nullptr);
    // attention
    attn_kernel<<<dim3(CL/64, CN, CB), 256, attn_smem>>>(cbv, pbv);

    // out @ Wc^T + bc -> t1
    sgemm<2><<<dim3(CH/128, CBL/128), 256>>>(pAtt, pWcT, CBL, CH, CH,
                                             bc, nullptr, nullptr, nullptr, pT1);
    // a = LN(t1 + x)
    ln_kernel<<<CBL, 256>>>(pT1, x, lnw, lnb, pA);
    // h1 = gelu(a @ W1^T + b1)
    sgemm<3><<<dim3(CH/128, CBL/128), 256>>>(pA, pW1T, CBL, CH, CH,
                                             b1, nullptr, nullptr, nullptr, pH1);
    // t2 = h1 @ W2^T + b2
    sgemm<2><<<dim3(CH/128, CBL/128), 256>>>(pH1, pW2T, CBL, CH, CH,
                                             b2, nullptr, nullptr, nullptr, pT2);
    // out = LN(t2 + a)
    ln_kernel<<<CBL, 256>>>(pT2, pA, lnw, lnb, out);
}

// round 2
// speedup vs baseline: 2.1319x; 2.1319x over previous
#include <cuda_runtime.h>
#include <math.h>
#include <stdint.h>

// Problem constants
#define CB 4
#define CL 2048
#define CH 512
#define CN 8
#define CD 64
#define CBL (CB*CL)   // 8192

// ---------------- scratch (device globals; no allocations allowed) ----------
__device__ float g_Wqkv[CH*3*CH];     // [h][which*512 + n*64 + d]
__device__ float g_WrP [CH*CH];       // [h][n*64+d]
__device__ float g_WcT [CH*CH];       // [k][j] = Wc[j][k]
__device__ float g_W1T [CH*CH];
__device__ float g_W2T [CH*CH];
__device__ float g_qc  [CB*CN*CL*CD]; // q + bq + content_bias
__device__ float g_k   [CB*CN*CL*CD];
__device__ float g_v   [CB*CN*CL*CD];
__device__ float g_r   [CN*CL*CD];
__device__ float g_att [CBL*CH];
__device__ float g_t1  [CBL*CH];
__device__ float g_a   [CBL*CH];
__device__ float g_h1  [CBL*CH];
__device__ float g_t2  [CBL*CH];

// ---------------- tf32 helpers ----------------
__device__ __forceinline__ uint32_t f2tf(float f) {
    uint32_t u;
    asm("cvt.rna.tf32.f32 %0, %1;" : "=r"(u) : "f"(f));
    return u;
}
__device__ __forceinline__ float tfc(float f) {   // tf32-rounded value as float bits
    return __uint_as_float(f2tf(f));
}
__device__ __forceinline__ void mma8(float& c0, float& c1, float& c2, float& c3,
                                     uint32_t a0, uint32_t a1, uint32_t a2, uint32_t a3,
                                     uint32_t b0, uint32_t b1) {
    asm("mma.sync.aligned.m16n8k8.row.col.f32.tf32.tf32.f32 "
        "{%0,%1,%2,%3},{%4,%5,%6,%7},{%8,%9},{%0,%1,%2,%3};"
        : "+f"(c0), "+f"(c1), "+f"(c2), "+f"(c3)
        : "r"(a0), "r"(a1), "r"(a2), "r"(a3), "r"(b0), "r"(b1));
}

// ---------------- weight repack ----------------
__global__ void pack_kernel(const float* __restrict__ Wq, const float* __restrict__ Wk,
                            const float* __restrict__ Wv, const float* __restrict__ Wr,
                            const float* __restrict__ Wc, const float* __restrict__ W1,
                            const float* __restrict__ W2)
{
    int idx = blockIdx.x*blockDim.x + threadIdx.x;
    int stride = gridDim.x*blockDim.x;
    for (int i = idx; i < CH*3*CH; i += stride) {
        int h = i / (3*CH);
        int j = i % (3*CH);
        int which = j >> 9;
        int rr = j & 511;
        int n = rr >> 6, d = rr & 63;
        const float* W = (which==0) ? Wq : (which==1) ? Wk : Wv;
        g_Wqkv[i] = W[(n*CH + h)*CD + d];
    }
    for (int i = idx; i < CH*CH; i += stride) {
        int h = i / CH, j = i % CH;
        int n = j >> 6, d = j & 63;
        g_WrP[i] = Wr[(n*CH + h)*CD + d];
        g_WcT[i] = Wc[j*CH + h];
        g_W1T[i] = W1[j*CH + h];
        g_W2T[i] = W2[j*CH + h];
    }
}

// ---------------- per-element epilogue ----------------
template<int EPI>
__device__ __forceinline__ void epi_store(int row, int col, float val, int Nc,
    const float* aux0, const float* aux1, const float* aux2, const float* aux3,
    float* out0)
{
    if (EPI == 0) {            // QKV -> g_qc / g_k / g_v in [b][n][l][d]
        int b = row >> 11, l = row & 2047;
        int which = col >> 9, rr = col & 511;
        int n = rr >> 6, d = rr & 63;
        int dst = ((b*CN + n)*CL + l)*CD + d;
        if (which == 0)      g_qc[dst] = val + aux0[rr] + aux3[rr];
        else if (which == 1) g_k[dst]  = val + aux1[rr];
        else                 g_v[dst]  = val + aux2[rr];
    } else if (EPI == 1) {     // R -> g_r [n][p][d]
        int n = col >> 6, d = col & 63;
        g_r[(n*CL + row)*CD + d] = val + aux0[col];
    } else if (EPI == 2) {
        out0[(size_t)row*Nc + col] = val + aux0[col];
    } else {
        float v2 = val + aux0[col];
        out0[(size_t)row*Nc + col] = 0.5f*v2*(1.0f + erff(v2*0.70710678118654752f));
    }
}

// ---------------- tf32 tensor-core GEMM: 128x64 tile, BK=32, 256 threads ----
template<int EPI>
__global__ void __launch_bounds__(256) tgemm(const float* __restrict__ A,
    const float* __restrict__ Bm, int M, int Nc, int K,
    const float* __restrict__ aux0, const float* __restrict__ aux1,
    const float* __restrict__ aux2, const float* __restrict__ aux3,
    float* __restrict__ out0)
{
    __shared__ float As[32][136];   // [k][m], pad 8 -> conflict-free frag LDS
    __shared__ float Bs[32][72];    // [k][n]
    const int t = threadIdx.x, lane = t & 31;
    const int w = t >> 5, wm = w >> 1, wn = w & 1;   // 4 x 2 warp grid
    const int qr = lane >> 2, qc = lane & 3;
    const int bm = blockIdx.y*128, bn = blockIdx.x*64;

    const int ar = t >> 1;          // A slab row 0..127
    const int af = (t & 1) * 4;     // A f4 idx base
    const int bk = t >> 3;          // B slab k 0..31
    const int bf = t & 7;           // B f4 idx base

    const float* Ap = A + (size_t)(bm + ar)*K;

    float4 aR[4]; float4 bR[2];
#pragma unroll
    for (int i = 0; i < 4; i++) aR[i] = *(const float4*)(Ap + (af+i)*4);
#pragma unroll
    for (int i = 0; i < 2; i++)
        bR[i] = *(const float4*)(Bm + (size_t)bk*Nc + bn + (bf + 8*i)*4);

    float c[2][4][4];
#pragma unroll
    for (int mi=0;mi<2;mi++)
#pragma unroll
        for (int ni=0;ni<4;ni++)
#pragma unroll
            for (int r=0;r<4;r++) c[mi][ni][r]=0.f;

    for (int k0 = 0; k0 < K; k0 += 32) {
#pragma unroll
        for (int i = 0; i < 4; i++) {
            int kk = (af+i)*4;
            As[kk+0][ar] = tfc(aR[i].x);
            As[kk+1][ar] = tfc(aR[i].y);
            As[kk+2][ar] = tfc(aR[i].z);
            As[kk+3][ar] = tfc(aR[i].w);
        }
#pragma unroll
        for (int i = 0; i < 2; i++) {
            float4 v = bR[i];
            v.x = tfc(v.x); v.y = tfc(v.y); v.z = tfc(v.z); v.w = tfc(v.w);
            *(float4*)&Bs[bk][(bf + 8*i)*4] = v;
        }
        __syncthreads();
        if (k0 + 32 < K) {
#pragma unroll
            for (int i = 0; i < 4; i++)
                aR[i] = *(const float4*)(Ap + k0 + 32 + (af+i)*4);
#pragma unroll
            for (int i = 0; i < 2; i++)
                bR[i] = *(const float4*)(Bm + (size_t)(k0 + 32 + bk)*Nc + bn + (bf + 8*i)*4);
        }
#pragma unroll
        for (int k8 = 0; k8 < 4; k8++) {
            uint32_t a[2][4], bb[4][2];
#pragma unroll
            for (int mi = 0; mi < 2; mi++) {
                int m = wm*32 + mi*16 + qr;
                a[mi][0] = __float_as_uint(As[k8*8+qc  ][m]);
                a[mi][1] = __float_as_uint(As[k8*8+qc  ][m+8]);
                a[mi][2] = __float_as_uint(As[k8*8+qc+4][m]);
                a[mi][3] = __float_as_uint(As[k8*8+qc+4][m+8]);
            }
#pragma unroll
            for (int ni = 0; ni < 4; ni++) {
                int nn = wn*32 + ni*8 + qr;
                bb[ni][0] = __float_as_uint(Bs[k8*8+qc  ][nn]);
                bb[ni][1] = __float_as_uint(Bs[k8*8+qc+4][nn]);
            }
#pragma unroll
            for (int mi = 0; mi < 2; mi++)
#pragma unroll
                for (int ni = 0; ni < 4; ni++)
                    mma8(c[mi][ni][0], c[mi][ni][1], c[mi][ni][2], c[mi][ni][3],
                         a[mi][0], a[mi][1], a[mi][2], a[mi][3],
                         bb[ni][0], bb[ni][1]);
        }
        __syncthreads();
    }

#pragma unroll
    for (int mi = 0; mi < 2; mi++) {
        int r0 = bm + wm*32 + mi*16 + qr;
#pragma unroll
        for (int ni = 0; ni < 4; ni++) {
            int c0v = bn + wn*32 + ni*8 + 2*qc;
            epi_store<EPI>(r0,   c0v,   c[mi][ni][0], Nc, aux0,aux1,aux2,aux3, out0);
            epi_store<EPI>(r0,   c0v+1, c[mi][ni][1], Nc, aux0,aux1,aux2,aux3, out0);
            epi_store<EPI>(r0+8, c0v,   c[mi][ni][2], Nc, aux0,aux1,aux2,aux3, out0);
            epi_store<EPI>(r0+8, c0v+1, c[mi][ni][3], Nc, aux0,aux1,aux2,aux3, out0);
        }
    }
}

// ---------------- mma flash attention with rel-shift ------------------------
// smem layout (floats):
#define SM_K   0        // Ks  [d=64][n=64]  stride 72
#define SM_V   4608     // Vs  [j=64][d=64]  stride 72
#define SM_R   9216     // Rs  [d=64][t=128] stride 136 (Qs [d][m] s72 aliased in prologue)
#define SM_BD  17920    // BDs [a=64][t]     stride 136 (Ps [j][m] s72 aliased)
#define SM_DLT 26624    // 64
#define ATT_SMEM_BYTES (26688*4)

__global__ void __launch_bounds__(128) attn_mma(const float* __restrict__ cbias,
                                                const float* __restrict__ pbias)
{
    extern __shared__ float sm[];
    const int t = threadIdx.x, lane = t & 31, w = t >> 5;
    const int qr = lane >> 2, qc = lane & 3;
    const int it = gridDim.x - 1 - blockIdx.x;     // heavy tiles first
    const int n = blockIdx.y, b = blockIdx.z;
    const int i0 = it * 64;
    const size_t bn_base = ((size_t)(b*CN + n))*CL;

    // ---- prologue: dlt + Q staging (Qs aliases SM_R) ----
    if (t < 64) sm[SM_DLT + t] = pbias[n*CD + t] - cbias[n*CD + t];
    {
        int row = t >> 1;
        const float* qp = g_qc + (bn_base + i0 + row)*CD;
#pragma unroll
        for (int i = 0; i < 8; i++) {
            int d = ((t & 1)*8 + i)*4;
            float4 qv = *(const float4*)(qp + d);
            sm[SM_R + (d+0)*72 + row] = qv.x;
            sm[SM_R + (d+1)*72 + row] = qv.y;
            sm[SM_R + (d+2)*72 + row] = qv.z;
            sm[SM_R + (d+3)*72 + row] = qv.w;
        }
    }
    __syncthreads();

    // build qc / qp fragments (scaled by 1/8, tf32-rounded)
    uint32_t qf[8][4], qpf[8][4];
    const int m0 = w*16 + qr;
#pragma unroll
    for (int k8 = 0; k8 < 8; k8++) {
        int kc = k8*8 + qc;
        float d0 = sm[SM_DLT + kc], d1 = sm[SM_DLT + kc + 4];
        float q00 = sm[SM_R + kc*72 + m0],     q01 = sm[SM_R + kc*72 + m0 + 8];
        float q10 = sm[SM_R + (kc+4)*72 + m0], q11 = sm[SM_R + (kc+4)*72 + m0 + 8];
        qf [k8][0] = f2tf(0.125f*q00);        qf [k8][1] = f2tf(0.125f*q01);
        qf [k8][2] = f2tf(0.125f*q10);        qf [k8][3] = f2tf(0.125f*q11);
        qpf[k8][0] = f2tf(0.125f*(q00+d0));   qpf[k8][1] = f2tf(0.125f*(q01+d0));
        qpf[k8][2] = f2tf(0.125f*(q10+d1));   qpf[k8][3] = f2tf(0.125f*(q11+d1));
    }

    float mx[2] = {-1e30f, -1e30f}, ls[2] = {0.f, 0.f};
    float O[8][4];
#pragma unroll
    for (int ni=0;ni<8;ni++)
#pragma unroll
        for (int r=0;r<4;r++) O[ni][r]=0.f;

    const int a_lo = w*16 + qr, a_hi = a_lo + 8;

    for (int j0 = 0; j0 <= i0; j0 += 64) {
        __syncthreads();
        // ---- stage K (transpose), V (direct), R (transpose, reversed+guard) ----
        {
            int row = t >> 1;
            const float* kp = g_k + (bn_base + j0 + row)*CD;
            const float* vp = g_v + (bn_base + j0 + row)*CD;
#pragma unroll
            for (int i = 0; i < 8; i++) {
                int d = ((t & 1)*8 + i)*4;
                float4 kv = *(const float4*)(kp + d);
                sm[SM_K + (d+0)*72 + row] = tfc(kv.x);
                sm[SM_K + (d+1)*72 + row] = tfc(kv.y);
                sm[SM_K + (d+2)*72 + row] = tfc(kv.z);
                sm[SM_K + (d+3)*72 + row] = tfc(kv.w);
                float4 vv = *(const float4*)(vp + d);
                vv.x = tfc(vv.x); vv.y = tfc(vv.y); vv.z = tfc(vv.z); vv.w = tfc(vv.w);
                *(float4*)&sm[SM_V + row*72 + d] = vv;
            }
            int trow = t;                       // 0..127
            int p = CL - 1 - (i0 - j0 - 63 + trow);
            bool ok = (p >= 0 && p < CL);
            const float* rp = g_r + ((size_t)n*CL + (ok ? p : 0))*CD;
#pragma unroll
            for (int i = 0; i < 16; i++) {
                float4 rv = ok ? *(const float4*)(rp + i*4) : make_float4(0.f,0.f,0.f,0.f);
                sm[SM_R + (i*4+0)*136 + trow] = tfc(rv.x);
                sm[SM_R + (i*4+1)*136 + trow] = tfc(rv.y);
                sm[SM_R + (i*4+2)*136 + trow] = tfc(rv.z);
                sm[SM_R + (i*4+3)*136 + trow] = tfc(rv.w);
            }
        }
        __syncthreads();

        // ---- BD = qp @ rr_tile^T  (warp-private t-window [16w, 16w+80)) ----
#pragma unroll
        for (int u = 0; u < 10; u++) {
            int nj = 2*w + u;
            float bd0=0.f, bd1=0.f, bd2=0.f, bd3=0.f;
#pragma unroll
            for (int k8 = 0; k8 < 8; k8++) {
                uint32_t b0 = __float_as_uint(sm[SM_R + (k8*8+qc  )*136 + nj*8 + qr]);
                uint32_t b1 = __float_as_uint(sm[SM_R + (k8*8+qc+4)*136 + nj*8 + qr]);
                mma8(bd0,bd1,bd2,bd3, qpf[k8][0],qpf[k8][1],qpf[k8][2],qpf[k8][3], b0,b1);
            }
            *(float2*)&sm[SM_BD + a_lo*136 + nj*8 + 2*qc] = make_float2(bd0, bd1);
            *(float2*)&sm[SM_BD + a_hi*136 + nj*8 + 2*qc] = make_float2(bd2, bd3);
        }
        __syncwarp();

        // ---- S = qc @ K^T ----
        float S[8][4];
#pragma unroll
        for (int ni=0;ni<8;ni++)
#pragma unroll
            for (int r=0;r<4;r++) S[ni][r]=0.f;
#pragma unroll
        for (int k8 = 0; k8 < 8; k8++) {
#pragma unroll
            for (int ni = 0; ni < 8; ni++) {
                uint32_t b0 = __float_as_uint(sm[SM_K + (k8*8+qc  )*72 + ni*8 + qr]);
                uint32_t b1 = __float_as_uint(sm[SM_K + (k8*8+qc+4)*72 + ni*8 + qr]);
                mma8(S[ni][0],S[ni][1],S[ni][2],S[ni][3],
                     qf[k8][0],qf[k8][1],qf[k8][2],qf[k8][3], b0,b1);
            }
        }
        // ---- gather rel-shift term: S[a][c] += BD[a][a-c+63] ----
#pragma unroll
        for (int ni = 0; ni < 8; ni++) {
            int cb = ni*8 + 2*qc;
            S[ni][0] += sm[SM_BD + a_lo*136 + (a_lo - cb + 63)];
            S[ni][1] += sm[SM_BD + a_lo*136 + (a_lo - cb + 62)];
            S[ni][2] += sm[SM_BD + a_hi*136 + (a_hi - cb + 63)];
            S[ni][3] += sm[SM_BD + a_hi*136 + (a_hi - cb + 62)];
        }
        // ---- causal mask on diagonal tile ----
        if (j0 == i0) {
#pragma unroll
            for (int ni = 0; ni < 8; ni++) {
                int cb = ni*8 + 2*qc;
                if (cb     > a_lo) S[ni][0] = -1e30f;
                if (cb + 1 > a_lo) S[ni][1] = -1e30f;
                if (cb     > a_hi) S[ni][2] = -1e30f;
                if (cb + 1 > a_hi) S[ni][3] = -1e30f;
            }
        }
        // ---- online softmax (rows owned by quads) ----
        float rmx0 = -1e30f, rmx1 = -1e30f;
#pragma unroll
        for (int ni = 0; ni < 8; ni++) {
            rmx0 = fmaxf(rmx0, fmaxf(S[ni][0], S[ni][1]));
            rmx1 = fmaxf(rmx1, fmaxf(S[ni][2], S[ni][3]));
        }
#pragma unroll
        for (int msk = 1; msk < 4; msk <<= 1) {
            rmx0 = fmaxf(rmx0, __shfl_xor_sync(0xffffffffu, rmx0, msk));
            rmx1 = fmaxf(rmx1, __shfl_xor_sync(0xffffffffu, rmx1, msk));
        }
        float mn0 = fmaxf(mx[0], rmx0), mn1 = fmaxf(mx[1], rmx1);
        float cr0 = __expf(mx[0] - mn0), cr1 = __expf(mx[1] - mn1);
        mx[0] = mn0; mx[1] = mn1;
        float rs0 = 0.f, rs1 = 0.f;
#pragma unroll
        for (int ni = 0; ni < 8; ni++) {
            S[ni][0] = __expf(S[ni][0] - mn0); rs0 += S[ni][0];
            S[ni][1] = __expf(S[ni][1] - mn0); rs0 += S[ni][1];
            S[ni][2] = __expf(S[ni][2] - mn1); rs1 += S[ni][2];
            S[ni][3] = __expf(S[ni][3] - mn1); rs1 += S[ni][3];
        }
#pragma unroll
        for (int msk = 1; msk < 4; msk <<= 1) {
            rs0 += __shfl_xor_sync(0xffffffffu, rs0, msk);
            rs1 += __shfl_xor_sync(0xffffffffu, rs1, msk);
        }
        ls[0] = ls[0]*cr0 + rs0;
        ls[1] = ls[1]*cr1 + rs1;
#pragma unroll
        for (int ni = 0; ni < 8; ni++) {
            O[ni][0] *= cr0; O[ni][1] *= cr0;
            O[ni][2] *= cr1; O[ni][3] *= cr1;
        }
        __syncthreads();   // all BD reads done before Ps overwrites the region
        // ---- write P (tf32) as [j][m] for PV A-fragments ----
#pragma unroll
        for (int ni = 0; ni < 8; ni++) {
            int col = ni*8 + 2*qc;
            sm[SM_BD + (col  )*72 + a_lo] = __uint_as_float(f2tf(S[ni][0]));
            sm[SM_BD + (col+1)*72 + a_lo] = __uint_as_float(f2tf(S[ni][1]));
            sm[SM_BD + (col  )*72 + a_hi] = __uint_as_float(f2tf(S[ni][2]));
            sm[SM_BD + (col+1)*72 + a_hi] = __uint_as_float(f2tf(S[ni][3]));
        }
        __syncwarp();
        // ---- O += P @ V ----
#pragma unroll
        for (int k8 = 0; k8 < 8; k8++) {
            uint32_t a0 = __float_as_uint(sm[SM_BD + (k8*8+qc  )*72 + m0]);
            uint32_t a1 = __float_as_uint(sm[SM_BD + (k8*8+qc  )*72 + m0 + 8]);
            uint32_t a2 = __float_as_uint(sm[SM_BD + (k8*8+qc+4)*72 + m0]);
            uint32_t a3 = __float_as_uint(sm[SM_BD + (k8*8+qc+4)*72 + m0 + 8]);
#pragma unroll
            for (int ni = 0; ni < 8; ni++) {
                uint32_t b0 = __float_as_uint(sm[SM_V + (k8*8+qc  )*72 + ni*8 + qr]);
                uint32_t b1 = __float_as_uint(sm[SM_V + (k8*8+qc+4)*72 + ni*8 + qr]);
                mma8(O[ni][0],O[ni][1],O[ni][2],O[ni][3], a0,a1,a2,a3, b0,b1);
            }
        }
    }

    // ---- epilogue: normalize + write [b][l][n*64+d] ----
    float inv0 = 1.f/ls[0], inv1 = 1.f/ls[1];
    size_t o0 = ((size_t)(b*CL + i0 + a_lo))*CH + n*CD;
    size_t o1 = o0 + 8*CH;
#pragma unroll
    for (int ni = 0; ni < 8; ni++) {
        int d = ni*8 + 2*qc;
        *(float2*)&g_att[o0 + d] = make_float2(O[ni][0]*inv0, O[ni][1]*inv0);
        *(float2*)&g_att[o1 + d] = make_float2(O[ni][2]*inv1, O[ni][3]*inv1);
    }
}

// ---------------- layernorm(X + R) --------------------------------------
__global__ void __launch_bounds__(256) ln_kernel(const float* __restrict__ X,
    const float* __restrict__ R, const float* __restrict__ w,
    const float* __restrict__ bb, float* __restrict__ out)
{
    __shared__ float sh[8];
    int row = blockIdx.x, t = threadIdx.x;
    const float* xp = X + (size_t)row*CH;
    const float* rp = R + (size_t)row*CH;
    float v0 = xp[t] + rp[t];
    float v1 = xp[t+256] + rp[t+256];

    float s = v0 + v1;
#pragma unroll
    for (int m=16;m;m>>=1) s += __shfl_xor_sync(0xffffffffu, s, m);
    if ((t & 31)==0) sh[t>>5] = s;
    __syncthreads();
    float tot = 0.f;
#pragma unroll
    for (int i=0;i<8;i++) tot += sh[i];
    __syncthreads();
    float mean = tot * (1.0f/CH);
    float d0 = v0 - mean, d1 = v1 - mean;
    float s2 = d0*d0 + d1*d1;
#pragma unroll
    for (int m=16;m;m>>=1) s2 += __shfl_xor_sync(0xffffffffu, s2, m);
    if ((t & 31)==0) sh[t>>5] = s2;
    __syncthreads();
    float tot2 = 0.f;
#pragma unroll
    for (int i=0;i<8;i++) tot2 += sh[i];
    float rstd = rsqrtf(tot2*(1.0f/CH) + 1e-12f);
    out[(size_t)row*CH + t]       = w[t]*d0*rstd + bb[t];
    out[(size_t)row*CH + t + 256] = w[t+256]*d1*rstd + bb[t+256];
}

// ---------------- launch ----------------------------------------------------
extern "C" void kernel_launch(void* const* d_in, const int* in_sizes, int n_in,
                              void* d_out, int out_size)
{
    const float* x   = (const float*)d_in[0];
    const float* pe  = (const float*)d_in[1];
    const float* Wq  = (const float*)d_in[2];
    const float* bq  = (const float*)d_in[3];
    const float* Wk  = (const float*)d_in[4];
    const float* bk  = (const float*)d_in[5];
    const float* Wv  = (const float*)d_in[6];
    const float* bv  = (const float*)d_in[7];
    const float* Wr  = (const float*)d_in[8];
    const float* br  = (const float*)d_in[9];
    const float* cbv = (const float*)d_in[10];
    const float* pbv = (const float*)d_in[11];
    const float* Wc  = (const float*)d_in[12];
    const float* bc  = (const float*)d_in[13];
    const float* W1  = (const float*)d_in[14];
    const float* b1  = (const float*)d_in[15];
    const float* W2  = (const float*)d_in[16];
    const float* b2  = (const float*)d_in[17];
    const float* lnw = (const float*)d_in[18];
    const float* lnb = (const float*)d_in[19];
    float* out = (float*)d_out;

    float *pWqkv, *pWrP, *pWcT, *pW1T, *pW2T, *pAtt, *pT1, *pA, *pH1, *pT2;
    cudaGetSymbolAddress((void**)&pWqkv, g_Wqkv);
    cudaGetSymbolAddress((void**)&pWrP,  g_WrP);
    cudaGetSymbolAddress((void**)&pWcT,  g_WcT);
    cudaGetSymbolAddress((void**)&pW1T,  g_W1T);
    cudaGetSymbolAddress((void**)&pW2T,  g_W2T);
    cudaGetSymbolAddress((void**)&pAtt,  g_att);
    cudaGetSymbolAddress((void**)&pT1,   g_t1);
    cudaGetSymbolAddress((void**)&pA,    g_a);
    cudaGetSymbolAddress((void**)&pH1,   g_h1);
    cudaGetSymbolAddress((void**)&pT2,   g_t2);

    cudaFuncSetAttribute(attn_mma,
        cudaFuncAttributeMaxDynamicSharedMemorySize, ATT_SMEM_BYTES);

    pack_kernel<<<128, 256>>>(Wq, Wk, Wv, Wr, Wc, W1, W2);

    // QKV: [8192,512] x [512,1536]
    tgemm<0><<<dim3(1536/64, CBL/128), 256>>>(x, pWqkv, CBL, 1536, CH,
                                              bq, bk, bv, cbv, nullptr);
    // R: [2048,512] x [512,512]
    tgemm<1><<<dim3(CH/64, CL/128), 256>>>(pe, pWrP, CL, CH, CH,
                                           br, nullptr, nullptr, nullptr, nullptr);
    // attention
    attn_mma<<<dim3(CL/64, CN, CB), 128, ATT_SMEM_BYTES>>>(cbv, pbv);

    // out @ Wc^T + bc -> t1
    tgemm<2><<<dim3(CH/64, CBL/128), 256>>>(pAtt, pWcT, CBL, CH, CH,
                                            bc, nullptr, nullptr, nullptr, pT1);
    // a = LN(t1 + x)
    ln_kernel<<<CBL, 256>>>(pT1, x, lnw, lnb, pA);
    // h1 = gelu(a @ W1^T + b1)
    tgemm<3><<<dim3(CH/64, CBL/128), 256>>>(pA, pW1T, CBL, CH, CH,
                                            b1, nullptr, nullptr, nullptr, pH1);
    // t2 = h1 @ W2^T + b2
    tgemm<2><<<dim3(CH/64, CBL/128), 256>>>(pH1, pW2T, CBL, CH, CH,
                                            b2, nullptr, nullptr, nullptr, pT2);
    // out = LN(t2 + a)
    ln_kernel<<<CBL, 256>>>(pT2, pA, lnw, lnb, out);
}

// round 8
// speedup vs baseline: 2.5825x; 1.2114x over previous
#include <cuda_runtime.h>
#include <math.h>
#include <stdint.h>

// Problem constants
#define CB 4
#define CL 2048
#define CH 512
#define CN 8
#define CD 64
#define CBL (CB*CL)   // 8192
#define RPAD 2240     // padded r rows per head: [0,64)=0 | [64,2112)=r | [2112,2240)=0

// ---------------- scratch (device globals; no allocations allowed) ----------
__device__ float g_Wqkv[CH*3*CH];     // [h][which*512 + n*64 + d]
__device__ float g_WrP [CH*CH];       // [h][n*64+d]
__device__ float g_WcT [CH*CH];       // [k][j] = Wc[j][k]
__device__ float g_W1T [CH*CH];
__device__ float g_W2T [CH*CH];
__device__ float g_qc  [CB*CN*CL*CD]; // q + bq + content_bias   [b][n][l][d]
__device__ float g_k   [CB*CN*CL*CD]; // [b][n][l][d]
__device__ float g_vT  [CB*CN*CD*CL]; // [b][n][d][l]  (transposed V)
__device__ float g_rp  [CN*RPAD*CD];  // zero-padded r: row index = p + 64
__device__ float g_att [CBL*CH];
__device__ float g_t1  [CBL*CH];
__device__ float g_a   [CBL*CH];
__device__ float g_h1  [CBL*CH];
__device__ float g_t2  [CBL*CH];

// ---------------- helpers ----------------
__device__ __forceinline__ void mma8(float& c0, float& c1, float& c2, float& c3,
                                     uint32_t a0, uint32_t a1, uint32_t a2, uint32_t a3,
                                     uint32_t b0, uint32_t b1) {
    asm("mma.sync.aligned.m16n8k8.row.col.f32.tf32.tf32.f32 "
        "{%0,%1,%2,%3},{%4,%5,%6,%7},{%8,%9},{%0,%1,%2,%3};"
        : "+f"(c0), "+f"(c1), "+f"(c2), "+f"(c3)
        : "r"(a0), "r"(a1), "r"(a2), "r"(a3), "r"(b0), "r"(b1));
}
#define FU(x) __float_as_uint(x)

__device__ __forceinline__ void cpa16(uint32_t smem_dst, const void* gmem_src) {
    asm volatile("cp.async.cg.shared.global [%0], [%1], 16;\n"
                 :: "r"(smem_dst), "l"(gmem_src));
}

// ---------------- weight repack + r border zeroing ----------------
__global__ void pack_kernel(const float* __restrict__ Wq, const float* __restrict__ Wk,
                            const float* __restrict__ Wv, const float* __restrict__ Wr,
                            const float* __restrict__ Wc, const float* __restrict__ W1,
                            const float* __restrict__ W2)
{
    int idx = blockIdx.x*blockDim.x + threadIdx.x;
    int stride = gridDim.x*blockDim.x;
    for (int i = idx; i < CH*3*CH; i += stride) {
        int h = i / (3*CH);
        int j = i % (3*CH);
        int which = j >> 9;
        int rr = j & 511;
        int n = rr >> 6, d = rr & 63;
        const float* W = (which==0) ? Wq : (which==1) ? Wk : Wv;
        g_Wqkv[i] = W[(n*CH + h)*CD + d];
    }
    for (int i = idx; i < CH*CH; i += stride) {
        int h = i / CH, j = i % CH;
        int n = j >> 6, d = j & 63;
        g_WrP[i] = Wr[(n*CH + h)*CD + d];
        g_WcT[i] = Wc[j*CH + h];
        g_W1T[i] = W1[j*CH + h];
        g_W2T[i] = W2[j*CH + h];
    }
    // zero borders of g_rp: rows [0,64) and [2112,2240) per head
    for (int i = idx; i < CN*192*CD; i += stride) {
        int n = i / (192*CD);
        int rr = i % (192*CD);
        int row = rr / CD, d = rr % CD;
        int arow = (row < 64) ? row : (row - 64 + 2112);
        g_rp[((size_t)n*RPAD + arow)*CD + d] = 0.f;
    }
}

// ---------------- per-element epilogue ----------------
template<int EPI>
__device__ __forceinline__ void epi_store(int row, int col, float val, int Nc,
    const float* aux0, const float* aux1, const float* aux2, const float* aux3,
    float* out0)
{
    if (EPI == 0) {            // QKV -> g_qc / g_k / g_vT
        int b = row >> 11, l = row & 2047;
        int which = col >> 9, rr = col & 511;
        int n = rr >> 6, d = rr & 63;
        if (which == 0)      g_qc[((size_t)(b*CN + n)*CL + l)*CD + d] = val + aux0[rr] + aux3[rr];
        else if (which == 1) g_k [((size_t)(b*CN + n)*CL + l)*CD + d] = val + aux1[rr];
        else                 g_vT[((size_t)(b*CN + n)*CD + d)*CL + l] = val + aux2[rr];
    } else if (EPI == 1) {     // R -> g_rp (row p at index p+64)
        int n = col >> 6, d = col & 63;
        g_rp[((size_t)n*RPAD + 64 + row)*CD + d] = val + aux0[col];
    } else if (EPI == 2) {
        out0[(size_t)row*Nc + col] = val + aux0[col];
    } else {
        float v2 = val + aux0[col];
        out0[(size_t)row*Nc + col] = 0.5f*v2*(1.0f + erff(v2*0.70710678118654752f));
    }
}

// ---------------- tf32 tensor-core GEMM: 128x64 tile, BK=32, 256 threads ----
template<int EPI>
__global__ void __launch_bounds__(256) tgemm(const float* __restrict__ A,
    const float* __restrict__ Bm, int M, int Nc, int K,
    const float* __restrict__ aux0, const float* __restrict__ aux1,
    const float* __restrict__ aux2, const float* __restrict__ aux3,
    float* __restrict__ out0)
{
    __shared__ float As[32][136];   // [k][m], pad -> conflict-free frag LDS
    __shared__ float Bs[32][72];    // [k][n]
    const int t = threadIdx.x, lane = t & 31;
    const int w = t >> 5, wm = w >> 1, wn = w & 1;   // 4 x 2 warp grid
    const int qr = lane >> 2, qc = lane & 3;
    const int bm = blockIdx.y*128, bn = blockIdx.x*64;

    const int ar = t >> 1;          // A slab row 0..127
    const int af = (t & 1) * 4;     // A f4 idx base
    const int bk = t >> 3;          // B slab k 0..31
    const int bf = t & 7;           // B f4 idx base

    const float* Ap = A + (size_t)(bm + ar)*K;

    float4 aR[4]; float4 bR[2];
#pragma unroll
    for (int i = 0; i < 4; i++) aR[i] = *(const float4*)(Ap + (af+i)*4);
#pragma unroll
    for (int i = 0; i < 2; i++)
        bR[i] = *(const float4*)(Bm + (size_t)bk*Nc + bn + (bf + 8*i)*4);

    float c[2][4][4];
#pragma unroll
    for (int mi=0;mi<2;mi++)
#pragma unroll
        for (int ni=0;ni<4;ni++)
#pragma unroll
            for (int r=0;r<4;r++) c[mi][ni][r]=0.f;

    for (int k0 = 0; k0 < K; k0 += 32) {
#pragma unroll
        for (int i = 0; i < 4; i++) {
            int kk = (af+i)*4;
            As[kk+0][ar] = aR[i].x;
            As[kk+1][ar] = aR[i].y;
            As[kk+2][ar] = aR[i].z;
            As[kk+3][ar] = aR[i].w;
        }
#pragma unroll
        for (int i = 0; i < 2; i++)
            *(float4*)&Bs[bk][(bf + 8*i)*4] = bR[i];
        __syncthreads();
        if (k0 + 32 < K) {
#pragma unroll
            for (int i = 0; i < 4; i++)
                aR[i] = *(const float4*)(Ap + k0 + 32 + (af+i)*4);
#pragma unroll
            for (int i = 0; i < 2; i++)
                bR[i] = *(const float4*)(Bm + (size_t)(k0 + 32 + bk)*Nc + bn + (bf + 8*i)*4);
        }
#pragma unroll
        for (int k8 = 0; k8 < 4; k8++) {
            uint32_t a[2][4], bb[4][2];
#pragma unroll
            for (int mi = 0; mi < 2; mi++) {
                int m = wm*32 + mi*16 + qr;
                a[mi][0] = FU(As[k8*8+qc  ][m]);
                a[mi][1] = FU(As[k8*8+qc  ][m+8]);
                a[mi][2] = FU(As[k8*8+qc+4][m]);
                a[mi][3] = FU(As[k8*8+qc+4][m+8]);
            }
#pragma unroll
            for (int ni = 0; ni < 4; ni++) {
                int nn = wn*32 + ni*8 + qr;
                bb[ni][0] = FU(Bs[k8*8+qc  ][nn]);
                bb[ni][1] = FU(Bs[k8*8+qc+4][nn]);
            }
#pragma unroll
            for (int mi = 0; mi < 2; mi++)
#pragma unroll
                for (int ni = 0; ni < 4; ni++)
                    mma8(c[mi][ni][0], c[mi][ni][1], c[mi][ni][2], c[mi][ni][3],
                         a[mi][0], a[mi][1], a[mi][2], a[mi][3],
                         bb[ni][0], bb[ni][1]);
        }
        __syncthreads();
    }

#pragma unroll
    for (int mi = 0; mi < 2; mi++) {
        int r0 = bm + wm*32 + mi*16 + qr;
#pragma unroll
        for (int ni = 0; ni < 4; ni++) {
            int c0v = bn + wn*32 + ni*8 + 2*qc;
            epi_store<EPI>(r0,   c0v,   c[mi][ni][0], Nc, aux0,aux1,aux2,aux3, out0);
            epi_store<EPI>(r0,   c0v+1, c[mi][ni][1], Nc, aux0,aux1,aux2,aux3, out0);
            epi_store<EPI>(r0+8, c0v,   c[mi][ni][2], Nc, aux0,aux1,aux2,aux3, out0);
            epi_store<EPI>(r0+8, c0v+1, c[mi][ni][3], Nc, aux0,aux1,aux2,aux3, out0);
        }
    }
}

// ---------------- mma flash attention with rel-shift ------------------------
// All smem operands row-major, k-pair trick (sigma permutation) -> LDS.64 frags.
// Layout (floats):
#define SA_K   0        // K  [n=64][k=64]  stride 72
#define SA_V   4608     // Vt [d=64][j=64]  stride 72
#define SA_R   9216     // R ring [slot=p&127][k=64] stride 72 (128 rows)
#define SA_BD  18432    // BD [a=64][t] stride 136; P [m][j] aliases (same rows)
#define SA_DLT 27136    // 64
#define ATT_SMEM_BYTES (27200*4)

__global__ void __launch_bounds__(128) attn_mma(const float* __restrict__ cbias,
                                                const float* __restrict__ pbias)
{
    extern __shared__ float sm[];
    const int t = threadIdx.x, lane = t & 31, w = t >> 5;   // 4 warps
    const int qr = lane >> 2, qc = lane & 3;
    const int it = gridDim.x - 1 - blockIdx.x;              // heavy tiles first
    const int n = blockIdx.y, b = blockIdx.z;
    const int i0 = it * 64;
    const size_t bnb = ((size_t)(b*CN + n))*CL;
    const size_t vtb = ((size_t)(b*CN + n))*CD;
    const uint32_t smb = (uint32_t)__cvta_generic_to_shared(sm);

    const int rowh = t >> 1, khalf = (t & 1)*32;

    // ---- dlt (pre-scaled by 1/8) ----
    if (t < 64) sm[SA_DLT + t] = 0.125f*(pbias[n*CD + t] - cbias[n*CD + t]);
    __syncthreads();

    // ---- Q fragments straight from gmem (sigma slots: a0<-2qc, a2<-2qc+1) ----
    const int m0 = w*16 + qr;         // a_lo
    const int a_lo = m0, a_hi = m0 + 8;
    float qf[8][4], qpf[8][4];
    {
        const float* q0p = g_qc + (bnb + i0 + m0)*CD;
        const float* q1p = q0p + 8*CD;
#pragma unroll
        for (int k8 = 0; k8 < 8; k8++) {
            float2 ql = *(const float2*)&q0p[k8*8 + 2*qc];
            float2 qh = *(const float2*)&q1p[k8*8 + 2*qc];
            float2 dl = *(const float2*)&sm[SA_DLT + k8*8 + 2*qc];
            qf[k8][0] = 0.125f*ql.x;  qf[k8][2] = 0.125f*ql.y;
            qf[k8][1] = 0.125f*qh.x;  qf[k8][3] = 0.125f*qh.y;
            qpf[k8][0] = qf[k8][0] + dl.x;  qpf[k8][2] = qf[k8][2] + dl.y;
            qpf[k8][1] = qf[k8][1] + dl.x;  qpf[k8][3] = qf[k8][3] + dl.y;
        }
    }

    float mx0 = -1e30f, mx1 = -1e30f, l0 = 0.f, l1 = 0.f;
    float O[8][4];
#pragma unroll
    for (int ni=0;ni<8;ni++)
#pragma unroll
        for (int r=0;r<4;r++) O[ni][r]=0.f;

    const int nT = i0/64 + 1;

    for (int jt = 0; jt < nT; jt++) {
        const int j0 = jt*64;
        const int PtC = CL + 62 - i0 + j0;   // r row for t-coord 0
        __syncthreads();                      // previous tile fully consumed
        // ---- stage K rows (direct copy) ----
        {
            const float* src = g_k + (bnb + j0 + rowh)*CD + khalf;
            uint32_t dst = smb + (uint32_t)(SA_K + rowh*72 + khalf)*4u;
#pragma unroll
            for (int i = 0; i < 8; i++) cpa16(dst + i*16, (const void*)(src + i*4));
        }
        // ---- stage Vt rows (direct copy) ----
        {
            const float* src = g_vT + (vtb + rowh)*CL + j0 + khalf;
            uint32_t dst = smb + (uint32_t)(SA_V + rowh*72 + khalf)*4u;
#pragma unroll
            for (int i = 0; i < 8; i++) cpa16(dst + i*16, (const void*)(src + i*4));
        }
        // ---- stage R ring rows ----
        if (jt == 0) {               // full 128-row window
            int p = PtC - t;
            const float* src = g_rp + ((size_t)n*RPAD + 64 + p)*CD;
            uint32_t dst = smb + (uint32_t)(SA_R + (p & 127)*72)*4u;
#pragma unroll
            for (int i = 0; i < 16; i++) cpa16(dst + i*16, (const void*)(src + i*4));
        } else {                     // only 64 new rows (window slides +64)
            int p = PtC - rowh;
            const float* src = g_rp + ((size_t)n*RPAD + 64 + p)*CD + khalf;
            uint32_t dst = smb + (uint32_t)(SA_R + (p & 127)*72 + khalf)*4u;
#pragma unroll
            for (int i = 0; i < 8; i++) cpa16(dst + i*16, (const void*)(src + i*4));
        }
        asm volatile("cp.async.commit_group;\n");
        asm volatile("cp.async.wait_group 0;\n");
        __syncthreads();

        // ---- BD = qp . r  (warp-private t-window [16w, 16w+80)) ----
#pragma unroll
        for (int u = 0; u < 10; u++) {
            const int tb = 16*w + u*8;
            const float* rrow = sm + SA_R + ((PtC - tb - qr) & 127)*72;
            float c0=0.f, c1=0.f, c2=0.f, c3=0.f;
#pragma unroll
            for (int k8 = 0; k8 < 8; k8++) {
                float2 bv = *(const float2*)&rrow[k8*8 + 2*qc];
                mma8(c0,c1,c2,c3,
                     FU(qpf[k8][0]),FU(qpf[k8][1]),FU(qpf[k8][2]),FU(qpf[k8][3]),
                     FU(bv.x),FU(bv.y));
            }
            *(float2*)&sm[SA_BD + a_lo*136 + tb + 2*qc] = make_float2(c0, c1);
            *(float2*)&sm[SA_BD + a_hi*136 + tb + 2*qc] = make_float2(c2, c3);
        }
        __syncwarp();

        // ---- S = qc . K^T ----
        float S[8][4];
#pragma unroll
        for (int ni=0;ni<8;ni++)
#pragma unroll
            for (int r=0;r<4;r++) S[ni][r]=0.f;
#pragma unroll
        for (int k8 = 0; k8 < 8; k8++)
#pragma unroll
            for (int ni = 0; ni < 8; ni++) {
                float2 bv = *(const float2*)&sm[SA_K + (ni*8+qr)*72 + k8*8 + 2*qc];
                mma8(S[ni][0],S[ni][1],S[ni][2],S[ni][3],
                     FU(qf[k8][0]),FU(qf[k8][1]),FU(qf[k8][2]),FU(qf[k8][3]),
                     FU(bv.x),FU(bv.y));
            }
        // ---- gather rel-shift: S[a][c] += BD[a][63 + a - c] ----
        {
            const int gb0 = SA_BD + a_lo*136 + a_lo + 63;
            const int gb1 = SA_BD + a_hi*136 + a_hi + 63;
#pragma unroll
            for (int ni = 0; ni < 8; ni++) {
                int cb = ni*8 + 2*qc;
                S[ni][0] += sm[gb0 - cb];
                S[ni][1] += sm[gb0 - cb - 1];
                S[ni][2] += sm[gb1 - cb];
                S[ni][3] += sm[gb1 - cb - 1];
            }
        }
        // ---- causal mask on diagonal tile ----
        if (j0 == i0) {
#pragma unroll
            for (int ni = 0; ni < 8; ni++) {
                int cb = ni*8 + 2*qc;
                if (cb     > a_lo) S[ni][0] = -1e30f;
                if (cb + 1 > a_lo) S[ni][1] = -1e30f;
                if (cb     > a_hi) S[ni][2] = -1e30f;
                if (cb + 1 > a_hi) S[ni][3] = -1e30f;
            }
        }
        // ---- online softmax (rows owned by quads) ----
        float rm0 = -1e30f, rm1 = -1e30f;
#pragma unroll
        for (int ni = 0; ni < 8; ni++) {
            rm0 = fmaxf(rm0, fmaxf(S[ni][0], S[ni][1]));
            rm1 = fmaxf(rm1, fmaxf(S[ni][2], S[ni][3]));
        }
#pragma unroll
        for (int msk = 1; msk < 4; msk <<= 1) {
            rm0 = fmaxf(rm0, __shfl_xor_sync(0xffffffffu, rm0, msk));
            rm1 = fmaxf(rm1, __shfl_xor_sync(0xffffffffu, rm1, msk));
        }
        float mn0 = fmaxf(mx0, rm0), mn1 = fmaxf(mx1, rm1);
        float cr0 = __expf(mx0 - mn0), cr1 = __expf(mx1 - mn1);
        mx0 = mn0; mx1 = mn1;
        float rs0 = 0.f, rs1 = 0.f;
#pragma unroll
        for (int ni = 0; ni < 8; ni++) {
            S[ni][0] = __expf(S[ni][0] - mn0); rs0 += S[ni][0];
            S[ni][1] = __expf(S[ni][1] - mn0); rs0 += S[ni][1];
            S[ni][2] = __expf(S[ni][2] - mn1); rs1 += S[ni][2];
            S[ni][3] = __expf(S[ni][3] - mn1); rs1 += S[ni][3];
        }
#pragma unroll
        for (int msk = 1; msk < 4; msk <<= 1) {
            rs0 += __shfl_xor_sync(0xffffffffu, rs0, msk);
            rs1 += __shfl_xor_sync(0xffffffffu, rs1, msk);
        }
        l0 = l0*cr0 + rs0;
        l1 = l1*cr1 + rs1;
#pragma unroll
        for (int ni = 0; ni < 8; ni++) {
            O[ni][0] *= cr0; O[ni][1] *= cr0;
            O[ni][2] *= cr1; O[ni][3] *= cr1;
        }
        __syncwarp();   // gathers (all lanes) done before P overwrites BD rows
        // ---- write P [m][j] (stride 136, aliases this warp's BD rows) ----
#pragma unroll
        for (int ni = 0; ni < 8; ni++) {
            int cb = ni*8 + 2*qc;
            *(float2*)&sm[SA_BD + a_lo*136 + cb] = make_float2(S[ni][0], S[ni][1]);
            *(float2*)&sm[SA_BD + a_hi*136 + cb] = make_float2(S[ni][2], S[ni][3]);
        }
        __syncwarp();
        // ---- O += P @ V ----
#pragma unroll
        for (int k8 = 0; k8 < 8; k8++) {
            float2 aL = *(const float2*)&sm[SA_BD + a_lo*136 + k8*8 + 2*qc];
            float2 aH = *(const float2*)&sm[SA_BD + a_hi*136 + k8*8 + 2*qc];
#pragma unroll
            for (int ni = 0; ni < 8; ni++) {
                float2 bv = *(const float2*)&sm[SA_V + (ni*8+qr)*72 + k8*8 + 2*qc];
                mma8(O[ni][0],O[ni][1],O[ni][2],O[ni][3],
                     FU(aL.x),FU(aH.x),FU(aL.y),FU(aH.y),
                     FU(bv.x),FU(bv.y));
            }
        }
    }

    // ---- epilogue: normalize + write [b][l][n*64+d] ----
    float inv0 = 1.f/l0, inv1 = 1.f/l1;
    size_t o0 = ((size_t)(b*CL + i0 + a_lo))*CH + n*CD;
    size_t o1 = o0 + 8*CH;
#pragma unroll
    for (int ni = 0; ni < 8; ni++) {
        int d = ni*8 + 2*qc;
        *(float2*)&g_att[o0 + d] = make_float2(O[ni][0]*inv0, O[ni][1]*inv0);
        *(float2*)&g_att[o1 + d] = make_float2(O[ni][2]*inv1, O[ni][3]*inv1);
    }
}

// ---------------- layernorm(X + R) --------------------------------------
__global__ void __launch_bounds__(256) ln_kernel(const float* __restrict__ X,
    const float* __restrict__ R, const float* __restrict__ w,
    const float* __restrict__ bb, float* __restrict__ out)
{
    __shared__ float sh[8];
    int row = blockIdx.x, t = threadIdx.x;
    const float* xp = X + (size_t)row*CH;
    const float* rp = R + (size_t)row*CH;
    float v0 = xp[t] + rp[t];
    float v1 = xp[t+256] + rp[t+256];

    float s = v0 + v1;
#pragma unroll
    for (int m=16;m;m>>=1) s += __shfl_xor_sync(0xffffffffu, s, m);
    if ((t & 31)==0) sh[t>>5] = s;
    __syncthreads();
    float tot = 0.f;
#pragma unroll
    for (int i=0;i<8;i++) tot += sh[i];
    __syncthreads();
    float mean = tot * (1.0f/CH);
    float d0 = v0 - mean, d1 = v1 - mean;
    float s2 = d0*d0 + d1*d1;
#pragma unroll
    for (int m=16;m;m>>=1) s2 += __shfl_xor_sync(0xffffffffu, s2, m);
    if ((t & 31)==0) sh[t>>5] = s2;
    __syncthreads();
    float tot2 = 0.f;
#pragma unroll
    for (int i=0;i<8;i++) tot2 += sh[i];
    float rstd = rsqrtf(tot2*(1.0f/CH) + 1e-12f);
    out[(size_t)row*CH + t]       = w[t]*d0*rstd + bb[t];
    out[(size_t)row*CH + t + 256] = w[t+256]*d1*rstd + bb[t+256];
}

// ---------------- launch ----------------------------------------------------
extern "C" void kernel_launch(void* const* d_in, const int* in_sizes, int n_in,
                              void* d_out, int out_size)
{
    const float* x   = (const float*)d_in[0];
    const float* pe  = (const float*)d_in[1];
    const float* Wq  = (const float*)d_in[2];
    const float* bq  = (const float*)d_in[3];
    const float* Wk  = (const float*)d_in[4];
    const float* bk  = (const float*)d_in[5];
    const float* Wv  = (const float*)d_in[6];
    const float* bv  = (const float*)d_in[7];
    const float* Wr  = (const float*)d_in[8];
    const float* br  = (const float*)d_in[9];
    const float* cbv = (const float*)d_in[10];
    const float* pbv = (const float*)d_in[11];
    const float* Wc  = (const float*)d_in[12];
    const float* bc  = (const float*)d_in[13];
    const float* W1  = (const float*)d_in[14];
    const float* b1  = (const float*)d_in[15];
    const float* W2  = (const float*)d_in[16];
    const float* b2  = (const float*)d_in[17];
    const float* lnw = (const float*)d_in[18];
    const float* lnb = (const float*)d_in[19];
    float* out = (float*)d_out;

    float *pWqkv, *pWrP, *pWcT, *pW1T, *pW2T, *pAtt, *pT1, *pA, *pH1, *pT2;
    cudaGetSymbolAddress((void**)&pWqkv, g_Wqkv);
    cudaGetSymbolAddress((void**)&pWrP,  g_WrP);
    cudaGetSymbolAddress((void**)&pWcT,  g_WcT);
    cudaGetSymbolAddress((void**)&pW1T,  g_W1T);
    cudaGetSymbolAddress((void**)&pW2T,  g_W2T);
    cudaGetSymbolAddress((void**)&pAtt,  g_att);
    cudaGetSymbolAddress((void**)&pT1,   g_t1);
    cudaGetSymbolAddress((void**)&pA,    g_a);
    cudaGetSymbolAddress((void**)&pH1,   g_h1);
    cudaGetSymbolAddress((void**)&pT2,   g_t2);

    cudaFuncSetAttribute(attn_mma,
        cudaFuncAttributeMaxDynamicSharedMemorySize, ATT_SMEM_BYTES);

    pack_kernel<<<128, 256>>>(Wq, Wk, Wv, Wr, Wc, W1, W2);

    // QKV: [8192,512] x [512,1536]
    tgemm<0><<<dim3(1536/64, CBL/128), 256>>>(x, pWqkv, CBL, 1536, CH,
                                              bq, bk, bv, cbv, nullptr);
    // R: [2048,512] x [512,512]
    tgemm<1><<<dim3(CH/64, CL/128), 256>>>(pe, pWrP, CL, CH, CH,
                                           br, nullptr, nullptr, nullptr, nullptr);
    // attention
    attn_mma<<<dim3(CL/64, CN, CB), 128, ATT_SMEM_BYTES>>>(cbv, pbv);

    // out @ Wc^T + bc -> t1
    tgemm<2><<<dim3(CH/64, CBL/128), 256>>>(pAtt, pWcT, CBL, CH, CH,
                                            bc, nullptr, nullptr, nullptr, pT1);
    // a = LN(t1 + x)
    ln_kernel<<<CBL, 256>>>(pT1, x, lnw, lnb, pA);
    // h1 = gelu(a @ W1^T + b1)
    tgemm<3><<<dim3(CH/64, CBL/128), 256>>>(pA, pW1T, CBL, CH, CH,
                                            b1, nullptr, nullptr, nullptr, pH1);
    // t2 = h1 @ W2^T + b2
    tgemm<2><<<dim3(CH/64, CBL/128), 256>>>(pH1, pW2T, CBL, CH, CH,
                                            b2, nullptr, nullptr, nullptr, pT2);
    // out = LN(t2 + a)
    ln_kernel<<<CBL, 256>>>(pT2, pA, lnw, lnb, out);
}

// round 11
// speedup vs baseline: 3.0808x; 1.1929x over previous
#include <cuda_runtime.h>
#include <math.h>
#include <stdint.h>

// Problem constants
#define CB 4
#define CL 2048
#define CH 512
#define CN 8
#define CD 64
#define CBL (CB*CL)   // 8192
#define RPAD 2240     // padded r rows per head: [0,64)=0 | [64,2112)=r | [2112,2240)=0

// ---------------- scratch (device globals; no allocations allowed) ----------
__device__ float g_Wqkv[CH*3*CH];     // [h][which*512 + n*64 + d]
__device__ float g_WrP [CH*CH];       // [h][n*64+d]
__device__ float g_WcT [CH*CH];       // [k][j] = Wc[j][k]
__device__ float g_W1T [CH*CH];
__device__ float g_W2T [CH*CH];
__device__ float g_qc  [CB*CN*CL*CD]; // q + bq + content_bias   [b][n][l][d]
__device__ float g_k   [CB*CN*CL*CD]; // [b][n][l][d]
__device__ float g_vT  [CB*CN*CD*CL]; // [b][n][d][l]  (transposed V)
__device__ float g_rp  [CN*RPAD*CD];  // zero-padded r: row index = p + 64
__device__ float g_att [CBL*CH];
__device__ float g_t1  [CBL*CH];
__device__ float g_a   [CBL*CH];
__device__ float g_h1  [CBL*CH];
__device__ float g_t2  [CBL*CH];

// ---------------- helpers ----------------
__device__ __forceinline__ void mma8(float& c0, float& c1, float& c2, float& c3,
                                     uint32_t a0, uint32_t a1, uint32_t a2, uint32_t a3,
                                     uint32_t b0, uint32_t b1) {
    asm("mma.sync.aligned.m16n8k8.row.col.f32.tf32.tf32.f32 "
        "{%0,%1,%2,%3},{%4,%5,%6,%7},{%8,%9},{%0,%1,%2,%3};"
        : "+f"(c0), "+f"(c1), "+f"(c2), "+f"(c3)
        : "r"(a0), "r"(a1), "r"(a2), "r"(a3), "r"(b0), "r"(b1));
}
#define FU(x) __float_as_uint(x)

__device__ __forceinline__ void cpa16(uint32_t smem_dst, const void* gmem_src) {
    asm volatile("cp.async.cg.shared.global [%0], [%1], 16;\n"
                 :: "r"(smem_dst), "l"(gmem_src));
}

// ---------------- weight repack + r border zeroing ----------------
__global__ void pack_kernel(const float* __restrict__ Wq, const float* __restrict__ Wk,
                            const float* __restrict__ Wv, const float* __restrict__ Wr,
                            const float* __restrict__ Wc, const float* __restrict__ W1,
                            const float* __restrict__ W2)
{
    int idx = blockIdx.x*blockDim.x + threadIdx.x;
    int stride = gridDim.x*blockDim.x;
    for (int i = idx; i < CH*3*CH; i += stride) {
        int h = i / (3*CH);
        int j = i % (3*CH);
        int which = j >> 9;
        int rr = j & 511;
        int n = rr >> 6, d = rr & 63;
        const float* W = (which==0) ? Wq : (which==1) ? Wk : Wv;
        g_Wqkv[i] = W[(n*CH + h)*CD + d];
    }
    for (int i = idx; i < CH*CH; i += stride) {
        int h = i / CH, j = i % CH;
        int n = j >> 6, d = j & 63;
        g_WrP[i] = Wr[(n*CH + h)*CD + d];
        g_WcT[i] = Wc[j*CH + h];
        g_W1T[i] = W1[j*CH + h];
        g_W2T[i] = W2[j*CH + h];
    }
    // zero borders of g_rp: rows [0,64) and [2112,2240) per head
    for (int i = idx; i < CN*192*CD; i += stride) {
        int n = i / (192*CD);
        int rr = i % (192*CD);
        int row = rr / CD, d = rr % CD;
        int arow = (row < 64) ? row : (row - 64 + 2112);
        g_rp[((size_t)n*RPAD + arow)*CD + d] = 0.f;
    }
}

// ---------------- per-element epilogue ----------------
template<int EPI>
__device__ __forceinline__ void epi_store(int row, int col, float val, int Nc,
    const float* aux0, const float* aux1, const float* aux2, const float* aux3,
    float* out0)
{
    if (EPI == 0) {            // QKV -> g_qc / g_k / g_vT
        int b = row >> 11, l = row & 2047;
        int which = col >> 9, rr = col & 511;
        int n = rr >> 6, d = rr & 63;
        if (which == 0)      g_qc[((size_t)(b*CN + n)*CL + l)*CD + d] = val + aux0[rr] + aux3[rr];
        else if (which == 1) g_k [((size_t)(b*CN + n)*CL + l)*CD + d] = val + aux1[rr];
        else                 g_vT[((size_t)(b*CN + n)*CD + d)*CL + l] = val + aux2[rr];
    } else if (EPI == 1) {     // R -> g_rp (row p at index p+64)
        int n = col >> 6, d = col & 63;
        g_rp[((size_t)n*RPAD + 64 + row)*CD + d] = val + aux0[col];
    } else if (EPI == 2) {
        out0[(size_t)row*Nc + col] = val + aux0[col];
    } else {
        float v2 = val + aux0[col];
        out0[(size_t)row*Nc + col] = 0.5f*v2*(1.0f + erff(v2*0.70710678118654752f));
    }
}

// ---------------- tf32 tensor-core GEMM: 128x64 tile, BK=32, 256 threads ----
template<int EPI>
__global__ void __launch_bounds__(256) tgemm(const float* __restrict__ A,
    const float* __restrict__ Bm, int M, int Nc, int K,
    const float* __restrict__ aux0, const float* __restrict__ aux1,
    const float* __restrict__ aux2, const float* __restrict__ aux3,
    float* __restrict__ out0)
{
    __shared__ float As[32][136];   // [k][m], pad -> conflict-free frag LDS
    __shared__ float Bs[32][72];    // [k][n]
    const int t = threadIdx.x, lane = t & 31;
    const int w = t >> 5, wm = w >> 1, wn = w & 1;   // 4 x 2 warp grid
    const int qr = lane >> 2, qc = lane & 3;
    const int bm = blockIdx.y*128, bn = blockIdx.x*64;

    const int ar = t >> 1;          // A slab row 0..127
    const int af = (t & 1) * 4;     // A f4 idx base
    const int bk = t >> 3;          // B slab k 0..31
    const int bf = t & 7;           // B f4 idx base

    const float* Ap = A + (size_t)(bm + ar)*K;

    float4 aR[4]; float4 bR[2];
#pragma unroll
    for (int i = 0; i < 4; i++) aR[i] = *(const float4*)(Ap + (af+i)*4);
#pragma unroll
    for (int i = 0; i < 2; i++)
        bR[i] = *(const float4*)(Bm + (size_t)bk*Nc + bn + (bf + 8*i)*4);

    float c[2][4][4];
#pragma unroll
    for (int mi=0;mi<2;mi++)
#pragma unroll
        for (int ni=0;ni<4;ni++)
#pragma unroll
            for (int r=0;r<4;r++) c[mi][ni][r]=0.f;

    for (int k0 = 0; k0 < K; k0 += 32) {
#pragma unroll
        for (int i = 0; i < 4; i++) {
            int kk = (af+i)*4;
            As[kk+0][ar] = aR[i].x;
            As[kk+1][ar] = aR[i].y;
            As[kk+2][ar] = aR[i].z;
            As[kk+3][ar] = aR[i].w;
        }
#pragma unroll
        for (int i = 0; i < 2; i++)
            *(float4*)&Bs[bk][(bf + 8*i)*4] = bR[i];
        __syncthreads();
        if (k0 + 32 < K) {
#pragma unroll
            for (int i = 0; i < 4; i++)
                aR[i] = *(const float4*)(Ap + k0 + 32 + (af+i)*4);
#pragma unroll
            for (int i = 0; i < 2; i++)
                bR[i] = *(const float4*)(Bm + (size_t)(k0 + 32 + bk)*Nc + bn + (bf + 8*i)*4);
        }
#pragma unroll
        for (int k8 = 0; k8 < 4; k8++) {
            uint32_t a[2][4], bb[4][2];
#pragma unroll
            for (int mi = 0; mi < 2; mi++) {
                int m = wm*32 + mi*16 + qr;
                a[mi][0] = FU(As[k8*8+qc  ][m]);
                a[mi][1] = FU(As[k8*8+qc  ][m+8]);
                a[mi][2] = FU(As[k8*8+qc+4][m]);
                a[mi][3] = FU(As[k8*8+qc+4][m+8]);
            }
#pragma unroll
            for (int ni = 0; ni < 4; ni++) {
                int nn = wn*32 + ni*8 + qr;
                bb[ni][0] = FU(Bs[k8*8+qc  ][nn]);
                bb[ni][1] = FU(Bs[k8*8+qc+4][nn]);
            }
#pragma unroll
            for (int mi = 0; mi < 2; mi++)
#pragma unroll
                for (int ni = 0; ni < 4; ni++)
                    mma8(c[mi][ni][0], c[mi][ni][1], c[mi][ni][2], c[mi][ni][3],
                         a[mi][0], a[mi][1], a[mi][2], a[mi][3],
                         bb[ni][0], bb[ni][1]);
        }
        __syncthreads();
    }

#pragma unroll
    for (int mi = 0; mi < 2; mi++) {
        int r0 = bm + wm*32 + mi*16 + qr;
#pragma unroll
        for (int ni = 0; ni < 4; ni++) {
            int c0v = bn + wn*32 + ni*8 + 2*qc;
            epi_store<EPI>(r0,   c0v,   c[mi][ni][0], Nc, aux0,aux1,aux2,aux3, out0);
            epi_store<EPI>(r0,   c0v+1, c[mi][ni][1], Nc, aux0,aux1,aux2,aux3, out0);
            epi_store<EPI>(r0+8, c0v,   c[mi][ni][2], Nc, aux0,aux1,aux2,aux3, out0);
            epi_store<EPI>(r0+8, c0v+1, c[mi][ni][3], Nc, aux0,aux1,aux2,aux3, out0);
        }
    }
}

// ---------------- mma flash attention: 128-row Q tile, 8 warps, -------------
// ---------------- double-buffered K/V + 256-row R ring, P in regs -----------
#define KS  72          // K/V/R row stride (phase-conflict-free for LDS.64 frags)
#define BDS 88          // BD band stride
#define SA_K0  0        // K buf0 [n=64][k]   4608
#define SA_K1  4608     // K buf1             4608
#define SA_V0  9216     // Vt buf0 [d=64][j]  4608
#define SA_V1  13824    // Vt buf1            4608
#define SA_R   18432    // R ring [slot=p&255][k]  256*72 = 18432
#define SA_BD  36864    // 8 x warp-private [16][88] = 11264
#define SA_DLT 48128    // 64
#define ATT_SMEM_FLOATS 48192
#define ATT_SMEM_BYTES (ATT_SMEM_FLOATS*4)

__global__ void __launch_bounds__(256, 1) attn_mma(const float* __restrict__ cbias,
                                                   const float* __restrict__ pbias)
{
    extern __shared__ float sm[];
    const int t = threadIdx.x, lane = t & 31, w = t >> 5;   // 8 warps
    const int qr = lane >> 2, qc = lane & 3;
    const int it = gridDim.x - 1 - blockIdx.x;              // heavy tiles first
    const int n = blockIdx.y, b = blockIdx.z;
    const int i0 = it * 128;
    const size_t bnb = ((size_t)(b*CN + n))*CL;
    const size_t vtb = ((size_t)(b*CN + n))*CD;
    const uint32_t smb = (uint32_t)__cvta_generic_to_shared(sm);
    const float* rbase = g_rp + (size_t)n*RPAD*CD + 64*CD;  // index by signed p

    // ---- dlt (pre-scaled by 1/8) ----
    if (t < 64) sm[SA_DLT + t] = 0.125f*(pbias[n*CD + t] - cbias[n*CD + t]);
    __syncthreads();

    // ---- Q fragments straight from gmem (sigma slots: a0<-2qc, a2<-2qc+1) ----
    const int m0 = 16*w + qr;         // local row (a_lo), 0..127
    float qf[8][4], qpf[8][4];
    {
        const float* q0p = g_qc + (bnb + i0 + m0)*CD;
        const float* q1p = q0p + 8*CD;
#pragma unroll
        for (int k8 = 0; k8 < 8; k8++) {
            float2 ql = *(const float2*)&q0p[k8*8 + 2*qc];
            float2 qh = *(const float2*)&q1p[k8*8 + 2*qc];
            float2 dl = *(const float2*)&sm[SA_DLT + k8*8 + 2*qc];
            qf[k8][0] = 0.125f*ql.x;  qf[k8][2] = 0.125f*ql.y;
            qf[k8][1] = 0.125f*qh.x;  qf[k8][3] = 0.125f*qh.y;
            qpf[k8][0] = qf[k8][0] + dl.x;  qpf[k8][2] = qf[k8][2] + dl.y;
            qpf[k8][1] = qf[k8][1] + dl.x;  qpf[k8][3] = qf[k8][3] + dl.y;
        }
    }

    const int nT = i0/64 + 2;
    const int PtC0 = CL + 62 - i0;          // PtC(jt) = PtC0 + 64*jt
    const int rq = t >> 2, ch = (t & 3)*16; // staging: row 0..63, 16-float chunk

    // ---- async stage issue for tile jt: K,V (buf jt&1) + new R ring rows ----
    auto issue = [&](int jt) {
        const int j0 = jt*64;
        {   // K rows [j0, j0+64)
            const float* src = g_k + (bnb + j0 + rq)*CD + ch;
            uint32_t dst = smb + (uint32_t)(((jt & 1) ? SA_K1 : SA_K0) + rq*KS + ch)*4u;
#pragma unroll
            for (int i = 0; i < 4; i++) cpa16(dst + i*16, (const void*)(src + i*4));
        }
        {   // Vt cols [j0, j0+64)
            const float* src = g_vT + (vtb + rq)*CL + j0 + ch;
            uint32_t dst = smb + (uint32_t)(((jt & 1) ? SA_V1 : SA_V0) + rq*KS + ch)*4u;
#pragma unroll
            for (int i = 0; i < 4; i++) cpa16(dst + i*16, (const void*)(src + i*4));
        }
        if (jt == 0) {      // initial R window: 192 rows, p = PtC0 - row
#pragma unroll
            for (int g = 0; g < 3; g++) {
                int id = t + 256*g;
                int row = id >> 2, c2 = (id & 3)*16;
                int p = PtC0 - row;
                const float* src = rbase + (ptrdiff_t)p*CD + c2;
                uint32_t dst = smb + (uint32_t)(SA_R + (p & 255)*KS + c2)*4u;
#pragma unroll
                for (int i = 0; i < 4; i++) cpa16(dst + i*16, (const void*)(src + i*4));
            }
        } else {            // 64 new rows: p = PtC(jt) - rq (complement slots)
            int p = PtC0 + 64*jt - rq;
            const float* src = rbase + (ptrdiff_t)p*CD + ch;
            uint32_t dst = smb + (uint32_t)(SA_R + (p & 255)*KS + ch)*4u;
#pragma unroll
            for (int i = 0; i < 4; i++) cpa16(dst + i*16, (const void*)(src + i*4));
        }
        asm volatile("cp.async.commit_group;\n");
    };

    float mx0 = -1e30f, mx1 = -1e30f, l0 = 0.f, l1 = 0.f;
    float O[8][4];
#pragma unroll
    for (int ni=0;ni<8;ni++)
#pragma unroll
        for (int r=0;r<4;r++) O[ni][r]=0.f;

    float* BDw = sm + SA_BD + w*(16*BDS);

    issue(0);
    for (int jt = 0; jt < nT; jt++) {
        if (jt + 1 < nT) { issue(jt + 1); asm volatile("cp.async.wait_group 1;\n"); }
        else             {                asm volatile("cp.async.wait_group 0;\n"); }
        __syncthreads();                  // tile jt's data visible to all warps

        const int jr = jt*64 - i0;        // tile col offset relative to rows
        if (jr <= 16*w + 15) {            // warp has >= 1 unmasked row
            const float* Kb = sm + ((jt & 1) ? SA_K1 : SA_K0);
            const float* Vb = sm + ((jt & 1) ? SA_V1 : SA_V0);
            const int PtC = PtC0 + 64*jt;

            // ---- BD = qp . r  (warp-private t-window [16w, 16w+80)) ----
#pragma unroll
            for (int u = 0; u < 10; u++) {
                const int tb = 16*w + u*8;
                float c0=0.f, c1=0.f, c2=0.f, c3=0.f;
#pragma unroll
                for (int k8 = 0; k8 < 8; k8++) {
                    const float* rrow = sm + SA_R + ((PtC - tb - qr) & 255)*KS;
                    float2 bv = *(const float2*)&rrow[k8*8 + 2*qc];
                    mma8(c0,c1,c2,c3,
                         FU(qpf[k8][0]),FU(qpf[k8][1]),FU(qpf[k8][2]),FU(qpf[k8][3]),
                         FU(bv.x),FU(bv.y));
                }
                *(float2*)&BDw[qr*BDS + u*8 + 2*qc]     = make_float2(c0, c1);
                *(float2*)&BDw[(qr+8)*BDS + u*8 + 2*qc] = make_float2(c2, c3);
            }
            __syncwarp();

            // ---- S = qc . K^T ----
            float S[8][4];
#pragma unroll
            for (int ni=0;ni<8;ni++)
#pragma unroll
                for (int r=0;r<4;r++) S[ni][r]=0.f;
#pragma unroll
            for (int k8 = 0; k8 < 8; k8++)
#pragma unroll
                for (int ni = 0; ni < 8; ni++) {
                    float2 bv = *(const float2*)&Kb[(ni*8+qr)*KS + k8*8 + 2*qc];
                    mma8(S[ni][0],S[ni][1],S[ni][2],S[ni][3],
                         FU(qf[k8][0]),FU(qf[k8][1]),FU(qf[k8][2]),FU(qf[k8][3]),
                         FU(bv.x),FU(bv.y));
                }
            // ---- gather rel-shift: S[a][c] += BD_local[r][63 + r - c] ----
            {
                const int gb0 = qr*BDS + qr + 63;        // row qr
                const int gb1 = (qr+8)*BDS + qr + 71;    // row qr+8
#pragma unroll
                for (int ni = 0; ni < 8; ni++) {
                    int cb = ni*8 + 2*qc;
                    S[ni][0] += BDw[gb0 - cb];
                    S[ni][1] += BDw[gb0 - cb - 1];
                    S[ni][2] += BDw[gb1 - cb];
                    S[ni][3] += BDw[gb1 - cb - 1];
                }
            }
            // ---- causal mask (near-diagonal warps only) ----
            if (jr + 63 > 16*w) {
                const int a_lo = m0, a_hi = m0 + 8;
#pragma unroll
                for (int ni = 0; ni < 8; ni++) {
                    int cj = ni*8 + 2*qc + jr;
                    if (cj     > a_lo) S[ni][0] = -1e30f;
                    if (cj + 1 > a_lo) S[ni][1] = -1e30f;
                    if (cj     > a_hi) S[ni][2] = -1e30f;
                    if (cj + 1 > a_hi) S[ni][3] = -1e30f;
                }
            }
            // ---- online softmax (rows owned by quads) ----
            float rm0 = -1e30f, rm1 = -1e30f;
#pragma unroll
            for (int ni = 0; ni < 8; ni++) {
                rm0 = fmaxf(rm0, fmaxf(S[ni][0], S[ni][1]));
                rm1 = fmaxf(rm1, fmaxf(S[ni][2], S[ni][3]));
            }
#pragma unroll
            for (int msk = 1; msk < 4; msk <<= 1) {
                rm0 = fmaxf(rm0, __shfl_xor_sync(0xffffffffu, rm0, msk));
                rm1 = fmaxf(rm1, __shfl_xor_sync(0xffffffffu, rm1, msk));
            }
            float mn0 = fmaxf(mx0, rm0), mn1 = fmaxf(mx1, rm1);
            float cr0 = __expf(mx0 - mn0), cr1 = __expf(mx1 - mn1);
            mx0 = mn0; mx1 = mn1;
            float rs0 = 0.f, rs1 = 0.f;
#pragma unroll
            for (int ni = 0; ni < 8; ni++) {
                S[ni][0] = __expf(S[ni][0] - mn0); rs0 += S[ni][0];
                S[ni][1] = __expf(S[ni][1] - mn0); rs0 += S[ni][1];
                S[ni][2] = __expf(S[ni][2] - mn1); rs1 += S[ni][2];
                S[ni][3] = __expf(S[ni][3] - mn1); rs1 += S[ni][3];
            }
#pragma unroll
            for (int msk = 1; msk < 4; msk <<= 1) {
                rs0 += __shfl_xor_sync(0xffffffffu, rs0, msk);
                rs1 += __shfl_xor_sync(0xffffffffu, rs1, msk);
            }
            l0 = l0*cr0 + rs0;
            l1 = l1*cr1 + rs1;
#pragma unroll
            for (int ni = 0; ni < 8; ni++) {
                O[ni][0] *= cr0; O[ni][1] *= cr0;
                O[ni][2] *= cr1; O[ni][3] *= cr1;
            }
            // ---- O += P @ V  (P = S fragments, straight from registers) ----
#pragma unroll
            for (int k8 = 0; k8 < 8; k8++)
#pragma unroll
                for (int ni = 0; ni < 8; ni++) {
                    float2 bv = *(const float2*)&Vb[(ni*8+qr)*KS + k8*8 + 2*qc];
                    mma8(O[ni][0],O[ni][1],O[ni][2],O[ni][3],
                         FU(S[k8][0]),FU(S[k8][2]),FU(S[k8][1]),FU(S[k8][3]),
                         FU(bv.x),FU(bv.y));
                }
        }
        __syncthreads();                  // all warps done with this buffer
    }

    // ---- epilogue: normalize + write [b][l][n*64+d] ----
    float inv0 = 1.f/l0, inv1 = 1.f/l1;
    size_t o0 = ((size_t)(b*CL + i0 + m0))*CH + n*CD;
    size_t o1 = o0 + 8*CH;
#pragma unroll
    for (int ni = 0; ni < 8; ni++) {
        int d = ni*8 + 2*qc;
        *(float2*)&g_att[o0 + d] = make_float2(O[ni][0]*inv0, O[ni][1]*inv0);
        *(float2*)&g_att[o1 + d] = make_float2(O[ni][2]*inv1, O[ni][3]*inv1);
    }
}

// ---------------- layernorm(X + R) --------------------------------------
__global__ void __launch_bounds__(256) ln_kernel(const float* __restrict__ X,
    const float* __restrict__ R, const float* __restrict__ w,
    const float* __restrict__ bb, float* __restrict__ out)
{
    __shared__ float sh[8];
    int row = blockIdx.x, t = threadIdx.x;
    const float* xp = X + (size_t)row*CH;
    const float* rp = R + (size_t)row*CH;
    float v0 = xp[t] + rp[t];
    float v1 = xp[t+256] + rp[t+256];

    float s = v0 + v1;
#pragma unroll
    for (int m=16;m;m>>=1) s += __shfl_xor_sync(0xffffffffu, s, m);
    if ((t & 31)==0) sh[t>>5] = s;
    __syncthreads();
    float tot = 0.f;
#pragma unroll
    for (int i=0;i<8;i++) tot += sh[i];
    __syncthreads();
    float mean = tot * (1.0f/CH);
    float d0 = v0 - mean, d1 = v1 - mean;
    float s2 = d0*d0 + d1*d1;
#pragma unroll
    for (int m=16;m;m>>=1) s2 += __shfl_xor_sync(0xffffffffu, s2, m);
    if ((t & 31)==0) sh[t>>5] = s2;
    __syncthreads();
    float tot2 = 0.f;
#pragma unroll
    for (int i=0;i<8;i++) tot2 += sh[i];
    float rstd = rsqrtf(tot2*(1.0f/CH) + 1e-12f);
    out[(size_t)row*CH + t]       = w[t]*d0*rstd + bb[t];
    out[(size_t)row*CH + t + 256] = w[t+256]*d1*rstd + bb[t+256];
}

// ---------------- launch ----------------------------------------------------
extern "C" void kernel_launch(void* const* d_in, const int* in_sizes, int n_in,
                              void* d_out, int out_size)
{
    const float* x   = (const float*)d_in[0];
    const float* pe  = (const float*)d_in[1];
    const float* Wq  = (const float*)d_in[2];
    const float* bq  = (const float*)d_in[3];
    const float* Wk  = (const float*)d_in[4];
    const float* bk  = (const float*)d_in[5];
    const float* Wv  = (const float*)d_in[6];
    const float* bv  = (const float*)d_in[7];
    const float* Wr  = (const float*)d_in[8];
    const float* br  = (const float*)d_in[9];
    const float* cbv = (const float*)d_in[10];
    const float* pbv = (const float*)d_in[11];
    const float* Wc  = (const float*)d_in[12];
    const float* bc  = (const float*)d_in[13];
    const float* W1  = (const float*)d_in[14];
    const float* b1  = (const float*)d_in[15];
    const float* W2  = (const float*)d_in[16];
    const float* b2  = (const float*)d_in[17];
    const float* lnw = (const float*)d_in[18];
    const float* lnb = (const float*)d_in[19];
    float* out = (float*)d_out;

    float *pWqkv, *pWrP, *pWcT, *pW1T, *pW2T, *pAtt, *pT1, *pA, *pH1, *pT2;
    cudaGetSymbolAddress((void**)&pWqkv, g_Wqkv);
    cudaGetSymbolAddress((void**)&pWrP,  g_WrP);
    cudaGetSymbolAddress((void**)&pWcT,  g_WcT);
    cudaGetSymbolAddress((void**)&pW1T,  g_W1T);
    cudaGetSymbolAddress((void**)&pW2T,  g_W2T);
    cudaGetSymbolAddress((void**)&pAtt,  g_att);
    cudaGetSymbolAddress((void**)&pT1,   g_t1);
    cudaGetSymbolAddress((void**)&pA,    g_a);
    cudaGetSymbolAddress((void**)&pH1,   g_h1);
    cudaGetSymbolAddress((void**)&pT2,   g_t2);

    cudaFuncSetAttribute(attn_mma,
        cudaFuncAttributeMaxDynamicSharedMemorySize, ATT_SMEM_BYTES);

    pack_kernel<<<128, 256>>>(Wq, Wk, Wv, Wr, Wc, W1, W2);

    // QKV: [8192,512] x [512,1536]
    tgemm<0><<<dim3(1536/64, CBL/128), 256>>>(x, pWqkv, CBL, 1536, CH,
                                              bq, bk, bv, cbv, nullptr);
    // R: [2048,512] x [512,512]
    tgemm<1><<<dim3(CH/64, CL/128), 256>>>(pe, pWrP, CL, CH, CH,
                                           br, nullptr, nullptr, nullptr, nullptr);
    // attention: 128-row Q tiles
    attn_mma<<<dim3(CL/128, CN, CB), 256, ATT_SMEM_BYTES>>>(cbv, pbv);

    // out @ Wc^T + bc -> t1
    tgemm<2><<<dim3(CH/64, CBL/128), 256>>>(pAtt, pWcT, CBL, CH, CH,
                                            bc, nullptr, nullptr, nullptr, pT1);
    // a = LN(t1 + x)
    ln_kernel<<<CBL, 256>>>(pT1, x, lnw, lnb, pA);
    // h1 = gelu(a @ W1^T + b1)
    tgemm<3><<<dim3(CH/64, CBL/128), 256>>>(pA, pW1T, CBL, CH, CH,
                                            b1, nullptr, nullptr, nullptr, pH1);
    // t2 = h1 @ W2^T + b2
    tgemm<2><<<dim3(CH/64, CBL/128), 256>>>(pH1, pW2T, CBL, CH, CH,
                                            b2, nullptr, nullptr, nullptr, pT2);
    // out = LN(t2 + a)
    ln_kernel<<<CBL, 256>>>(pT2, pA, lnw, lnb, out);
}

// round 13
// speedup vs baseline: 3.2543x; 1.0563x over previous
#include <cuda_runtime.h>
#include <math.h>
#include <stdint.h>

// Problem constants
#define CB 4
#define CL 2048
#define CH 512
#define CN 8
#define CD 64
#define CBL (CB*CL)   // 8192
#define RPAD 2240     // padded r rows per head: [0,64)=0 | [64,2112)=r | [2112,2240)=0

// ---------------- scratch (device globals; no allocations allowed) ----------
__device__ float g_Wqkv[3*CH*CH];     // [j=which*512+n*64+d][h]   (B^T layout)
__device__ float g_WrP [CH*CH];       // [j=n*64+d][h]
__device__ float g_qc  [CB*CN*CL*CD]; // q + bq + content_bias   [b][n][l][d]
__device__ float g_k   [CB*CN*CL*CD]; // [b][n][l][d]
__device__ float g_vT  [CB*CN*CD*CL]; // [b][n][d][l]  (transposed V)
__device__ float g_rp  [CN*RPAD*CD];  // zero-padded r: row index = p + 64
__device__ float g_att [CBL*CH];
__device__ float g_t1  [CBL*CH];
__device__ float g_a   [CBL*CH];
__device__ float g_h1  [CBL*CH];
__device__ float g_t2  [CBL*CH];

// ---------------- helpers ----------------
__device__ __forceinline__ void mma8(float& c0, float& c1, float& c2, float& c3,
                                     uint32_t a0, uint32_t a1, uint32_t a2, uint32_t a3,
                                     uint32_t b0, uint32_t b1) {
    asm("mma.sync.aligned.m16n8k8.row.col.f32.tf32.tf32.f32 "
        "{%0,%1,%2,%3},{%4,%5,%6,%7},{%8,%9},{%0,%1,%2,%3};"
        : "+f"(c0), "+f"(c1), "+f"(c2), "+f"(c3)
        : "r"(a0), "r"(a1), "r"(a2), "r"(a3), "r"(b0), "r"(b1));
}
#define FU(x) __float_as_uint(x)

__device__ __forceinline__ void cpa16(uint32_t smem_dst, const void* gmem_src) {
    asm volatile("cp.async.cg.shared.global [%0], [%1], 16;\n"
                 :: "r"(smem_dst), "l"(gmem_src));
}

// ---------------- weight repack + r border zeroing ----------------
__global__ void pack_kernel(const float* __restrict__ Wq, const float* __restrict__ Wk,
                            const float* __restrict__ Wv, const float* __restrict__ Wr)
{
    int idx = blockIdx.x*blockDim.x + threadIdx.x;
    int stride = gridDim.x*blockDim.x;
    // g_Wqkv[j][h], j = which*512 + n*64 + d
    for (int i = idx; i < 3*CH*CH; i += stride) {
        int j = i >> 9;           // /512
        int h = i & 511;
        int which = j >> 9;
        int rr = j & 511;
        int n = rr >> 6, d = rr & 63;
        const float* W = (which==0) ? Wq : (which==1) ? Wk : Wv;
        g_Wqkv[i] = W[(n*CH + h)*CD + d];
    }
    for (int i = idx; i < CH*CH; i += stride) {
        int j = i >> 9, h = i & 511;
        int n = j >> 6, d = j & 63;
        g_WrP[i] = Wr[(n*CH + h)*CD + d];
    }
    // zero borders of g_rp: rows [0,64) and [2112,2240) per head
    for (int i = idx; i < CN*192*CD; i += stride) {
        int n = i / (192*CD);
        int rr = i % (192*CD);
        int row = rr / CD, d = rr % CD;
        int arow = (row < 64) ? row : (row - 64 + 2112);
        g_rp[((size_t)n*RPAD + arow)*CD + d] = 0.f;
    }
}

// ---------------- per-element epilogue ----------------
template<int EPI>
__device__ __forceinline__ void epi_store(int row, int col, float val, int Nc,
    const float* aux0, const float* aux1, const float* aux2, const float* aux3,
    float* out0)
{
    if (EPI == 0) {            // QKV -> g_qc / g_k / g_vT
        int b = row >> 11, l = row & 2047;
        int which = col >> 9, rr = col & 511;
        int n = rr >> 6, d = rr & 63;
        if (which == 0)      g_qc[((size_t)(b*CN + n)*CL + l)*CD + d] = val + aux0[rr] + aux3[rr];
        else if (which == 1) g_k [((size_t)(b*CN + n)*CL + l)*CD + d] = val + aux1[rr];
        else                 g_vT[((size_t)(b*CN + n)*CD + d)*CL + l] = val + aux2[rr];
    } else if (EPI == 1) {     // R -> g_rp (row p at index p+64)
        int n = col >> 6, d = col & 63;
        g_rp[((size_t)n*RPAD + 64 + row)*CD + d] = val + aux0[col];
    } else if (EPI == 2) {
        out0[(size_t)row*Nc + col] = val + aux0[col];
    } else {
        float v2 = val + aux0[col];
        out0[(size_t)row*Nc + col] = 0.5f*v2*(1.0f + erff(v2*0.70710678118654752f));
    }
}

// ---------------- tf32 GEMM: 128x128 tile, BK=32, sigma-packed, cp.async ----
// A [m][k] row-major smem, B [n][k] row-major smem (B input is B^T = [n][K]).
#define TGS   40          // smem row stride (floats): conflict-free LDS.64
#define TG_A0 0           // 128*40 = 5120
#define TG_A1 5120
#define TG_B0 10240
#define TG_B1 15360
#define TG_SMEM_BYTES (20480*4)   // 80 KB -> 2 CTAs/SM

template<int EPI>
__global__ void __launch_bounds__(256, 2) tgemm(const float* __restrict__ A,
    const float* __restrict__ Bm, int M, int Nc, int K,
    const float* __restrict__ aux0, const float* __restrict__ aux1,
    const float* __restrict__ aux2, const float* __restrict__ aux3,
    float* __restrict__ out0)
{
    extern __shared__ float smg[];
    const int t = threadIdx.x, lane = t & 31;
    const int w = t >> 5, wm = w >> 1, wn = w & 1;   // 4 x 2 warp grid, 32x64 subtile
    const int qr = lane >> 2, qc = lane & 3;
    const int bm = blockIdx.y*128, bn = blockIdx.x*128;
    const uint32_t smb = (uint32_t)__cvta_generic_to_shared(smg);

    const int srow = t >> 1, scol = (t & 1)*16;      // staging: row, 16-float chunk
    const int NS = K >> 5;                            // k-stages

    auto issue = [&](int s) {
        const int k0 = s << 5;
        {   // A rows [bm, bm+128)
            const float* src = A + (size_t)(bm + srow)*K + k0 + scol;
            uint32_t dst = smb + (uint32_t)(((s & 1) ? TG_A1 : TG_A0) + srow*TGS + scol)*4u;
            cpa16(dst,      (const void*)(src));
            cpa16(dst + 16, (const void*)(src + 4));
            cpa16(dst + 32, (const void*)(src + 8));
            cpa16(dst + 48, (const void*)(src + 12));
        }
        {   // B rows [bn, bn+128)
            const float* src = Bm + (size_t)(bn + srow)*K + k0 + scol;
            uint32_t dst = smb + (uint32_t)(((s & 1) ? TG_B1 : TG_B0) + srow*TGS + scol)*4u;
            cpa16(dst,      (const void*)(src));
            cpa16(dst + 16, (const void*)(src + 4));
            cpa16(dst + 32, (const void*)(src + 8));
            cpa16(dst + 48, (const void*)(src + 12));
        }
        asm volatile("cp.async.commit_group;\n");
    };

    float c[2][8][4];
#pragma unroll
    for (int mi=0;mi<2;mi++)
#pragma unroll
        for (int ni=0;ni<8;ni++)
#pragma unroll
            for (int r=0;r<4;r++) c[mi][ni][r]=0.f;

    issue(0);
    issue(1);
    for (int s = 0; s < NS; s++) {
        if (s + 1 < NS) asm volatile("cp.async.wait_group 1;\n");
        else            asm volatile("cp.async.wait_group 0;\n");
        __syncthreads();
        const float* Ab = smg + ((s & 1) ? TG_A1 : TG_A0);
        const float* Bb = smg + ((s & 1) ? TG_B1 : TG_B0);
#pragma unroll
        for (int k8 = 0; k8 < 4; k8++) {
            uint32_t a[2][4];
#pragma unroll
            for (int mi = 0; mi < 2; mi++) {
                int m = wm*32 + mi*16 + qr;
                float2 lo = *(const float2*)&Ab[m*TGS + k8*8 + 2*qc];
                float2 hi = *(const float2*)&Ab[(m+8)*TGS + k8*8 + 2*qc];
                a[mi][0] = FU(lo.x); a[mi][1] = FU(hi.x);
                a[mi][2] = FU(lo.y); a[mi][3] = FU(hi.y);
            }
#pragma unroll
            for (int ni = 0; ni < 8; ni++) {
                int nn = wn*64 + ni*8 + qr;
                float2 bv = *(const float2*)&Bb[nn*TGS + k8*8 + 2*qc];
                mma8(c[0][ni][0], c[0][ni][1], c[0][ni][2], c[0][ni][3],
                     a[0][0], a[0][1], a[0][2], a[0][3], FU(bv.x), FU(bv.y));
                mma8(c[1][ni][0], c[1][ni][1], c[1][ni][2], c[1][ni][3],
                     a[1][0], a[1][1], a[1][2], a[1][3], FU(bv.x), FU(bv.y));
            }
        }
        __syncthreads();
        if (s + 2 < NS) issue(s + 2);
    }

#pragma unroll
    for (int mi = 0; mi < 2; mi++) {
        int r0 = bm + wm*32 + mi*16 + qr;
#pragma unroll
        for (int ni = 0; ni < 8; ni++) {
            int c0v = bn + wn*64 + ni*8 + 2*qc;
            epi_store<EPI>(r0,   c0v,   c[mi][ni][0], Nc, aux0,aux1,aux2,aux3, out0);
            epi_store<EPI>(r0,   c0v+1, c[mi][ni][1], Nc, aux0,aux1,aux2,aux3, out0);
            epi_store<EPI>(r0+8, c0v,   c[mi][ni][2], Nc, aux0,aux1,aux2,aux3, out0);
            epi_store<EPI>(r0+8, c0v+1, c[mi][ni][3], Nc, aux0,aux1,aux2,aux3, out0);
        }
    }
}

// ---------------- mma flash attention: 128-row Q tile, 8 warps, -------------
// ---------------- double-buffered K/V + 256-row R ring, P in regs -----------
#define KS  72          // K/V/R row stride (phase-conflict-free for LDS.64 frags)
#define BDS 88          // BD band stride
#define SA_K0  0        // K buf0 [n=64][k]   4608
#define SA_K1  4608     // K buf1             4608
#define SA_V0  9216     // Vt buf0 [d=64][j]  4608
#define SA_V1  13824    // Vt buf1            4608
#define SA_R   18432    // R ring [slot=p&255][k]  256*72 = 18432
#define SA_BD  36864    // 8 x warp-private [16][88] = 11264
#define SA_DLT 48128    // 64
#define ATT_SMEM_FLOATS 48192
#define ATT_SMEM_BYTES (ATT_SMEM_FLOATS*4)

__global__ void __launch_bounds__(256, 1) attn_mma(const float* __restrict__ cbias,
                                                   const float* __restrict__ pbias)
{
    extern __shared__ float sm[];
    const int t = threadIdx.x, lane = t & 31, w = t >> 5;   // 8 warps
    const int qr = lane >> 2, qc = lane & 3;
    const int it = gridDim.x - 1 - blockIdx.x;              // heavy tiles first
    const int n = blockIdx.y, b = blockIdx.z;
    const int i0 = it * 128;
    const size_t bnb = ((size_t)(b*CN + n))*CL;
    const size_t vtb = ((size_t)(b*CN + n))*CD;
    const uint32_t smb = (uint32_t)__cvta_generic_to_shared(sm);
    const float* rbase = g_rp + (size_t)n*RPAD*CD + 64*CD;  // index by signed p

    // ---- dlt (pre-scaled by 1/8) ----
    if (t < 64) sm[SA_DLT + t] = 0.125f*(pbias[n*CD + t] - cbias[n*CD + t]);
    __syncthreads();

    // ---- Q fragments straight from gmem (sigma slots: a0<-2qc, a2<-2qc+1) ----
    const int m0 = 16*w + qr;         // local row (a_lo), 0..127
    float qf[8][4], qpf[8][4];
    {
        const float* q0p = g_qc + (bnb + i0 + m0)*CD;
        const float* q1p = q0p + 8*CD;
#pragma unroll
        for (int k8 = 0; k8 < 8; k8++) {
            float2 ql = *(const float2*)&q0p[k8*8 + 2*qc];
            float2 qh = *(const float2*)&q1p[k8*8 + 2*qc];
            float2 dl = *(const float2*)&sm[SA_DLT + k8*8 + 2*qc];
            qf[k8][0] = 0.125f*ql.x;  qf[k8][2] = 0.125f*ql.y;
            qf[k8][1] = 0.125f*qh.x;  qf[k8][3] = 0.125f*qh.y;
            qpf[k8][0] = qf[k8][0] + dl.x;  qpf[k8][2] = qf[k8][2] + dl.y;
            qpf[k8][1] = qf[k8][1] + dl.x;  qpf[k8][3] = qf[k8][3] + dl.y;
        }
    }

    const int nT = i0/64 + 2;
    const int PtC0 = CL + 62 - i0;          // PtC(jt) = PtC0 + 64*jt
    const int rq = t >> 2, ch = (t & 3)*16; // staging: row 0..63, 16-float chunk

    // ---- async stage issue for tile jt: K,V (buf jt&1) + new R ring rows ----
    auto issue = [&](int jt) {
        const int j0 = jt*64;
        {   // K rows [j0, j0+64)
            const float* src = g_k + (bnb + j0 + rq)*CD + ch;
            uint32_t dst = smb + (uint32_t)(((jt & 1) ? SA_K1 : SA_K0) + rq*KS + ch)*4u;
#pragma unroll
            for (int i = 0; i < 4; i++) cpa16(dst + i*16, (const void*)(src + i*4));
        }
        {   // Vt cols [j0, j0+64)
            const float* src = g_vT + (vtb + rq)*CL + j0 + ch;
            uint32_t dst = smb + (uint32_t)(((jt & 1) ? SA_V1 : SA_V0) + rq*KS + ch)*4u;
#pragma unroll
            for (int i = 0; i < 4; i++) cpa16(dst + i*16, (const void*)(src + i*4));
        }
        if (jt == 0) {      // initial R window: 192 rows, p = PtC0 - row
#pragma unroll
            for (int g = 0; g < 3; g++) {
                int id = t + 256*g;
                int row = id >> 2, c2 = (id & 3)*16;
                int p = PtC0 - row;
                const float* src = rbase + (ptrdiff_t)p*CD + c2;
                uint32_t dst = smb + (uint32_t)(SA_R + (p & 255)*KS + c2)*4u;
#pragma unroll
                for (int i = 0; i < 4; i++) cpa16(dst + i*16, (const void*)(src + i*4));
            }
        } else {            // 64 new rows: p = PtC(jt) - rq (complement slots)
            int p = PtC0 + 64*jt - rq;
            const float* src = rbase + (ptrdiff_t)p*CD + ch;
            uint32_t dst = smb + (uint32_t)(SA_R + (p & 255)*KS + ch)*4u;
#pragma unroll
            for (int i = 0; i < 4; i++) cpa16(dst + i*16, (const void*)(src + i*4));
        }
        asm volatile("cp.async.commit_group;\n");
    };

    float mx0 = -1e30f, mx1 = -1e30f, l0 = 0.f, l1 = 0.f;
    float O[8][4];
#pragma unroll
    for (int ni=0;ni<8;ni++)
#pragma unroll
        for (int r=0;r<4;r++) O[ni][r]=0.f;

    float* BDw = sm + SA_BD + w*(16*BDS);

    issue(0);
    for (int jt = 0; jt < nT; jt++) {
        if (jt + 1 < nT) { issue(jt + 1); asm volatile("cp.async.wait_group 1;\n"); }
        else             {                asm volatile("cp.async.wait_group 0;\n"); }
        __syncthreads();                  // tile jt's data visible to all warps

        const int jr = jt*64 - i0;        // tile col offset relative to rows
        if (jr <= 16*w + 15) {            // warp has >= 1 unmasked row
            const float* Kb = sm + ((jt & 1) ? SA_K1 : SA_K0);
            const float* Vb = sm + ((jt & 1) ? SA_V1 : SA_V0);
            const int PtC = PtC0 + 64*jt;

            // ---- BD = qp . r  (warp-private t-window [16w, 16w+80)) ----
#pragma unroll
            for (int u = 0; u < 10; u++) {
                const int tb = 16*w + u*8;
                float c0=0.f, c1=0.f, c2=0.f, c3=0.f;
#pragma unroll
                for (int k8 = 0; k8 < 8; k8++) {
                    const float* rrow = sm + SA_R + ((PtC - tb - qr) & 255)*KS;
                    float2 bv = *(const float2*)&rrow[k8*8 + 2*qc];
                    mma8(c0,c1,c2,c3,
                         FU(qpf[k8][0]),FU(qpf[k8][1]),FU(qpf[k8][2]),FU(qpf[k8][3]),
                         FU(bv.x),FU(bv.y));
                }
                *(float2*)&BDw[qr*BDS + u*8 + 2*qc]     = make_float2(c0, c1);
                *(float2*)&BDw[(qr+8)*BDS + u*8 + 2*qc] = make_float2(c2, c3);
            }
            __syncwarp();

            // ---- S = qc . K^T ----
            float S[8][4];
#pragma unroll
            for (int ni=0;ni<8;ni++)
#pragma unroll
                for (int r=0;r<4;r++) S[ni][r]=0.f;
#pragma unroll
            for (int k8 = 0; k8 < 8; k8++)
#pragma unroll
                for (int ni = 0; ni < 8; ni++) {
                    float2 bv = *(const float2*)&Kb[(ni*8+qr)*KS + k8*8 + 2*qc];
                    mma8(S[ni][0],S[ni][1],S[ni][2],S[ni][3],
                         FU(qf[k8][0]),FU(qf[k8][1]),FU(qf[k8][2]),FU(qf[k8][3]),
                         FU(bv.x),FU(bv.y));
                }
            // ---- gather rel-shift: S[a][c] += BD_local[r][63 + r - c] ----
            {
                const int gb0 = qr*BDS + qr + 63;        // row qr
                const int gb1 = (qr+8)*BDS + qr + 71;    // row qr+8
#pragma unroll
                for (int ni = 0; ni < 8; ni++) {
                    int cb = ni*8 + 2*qc;
                    S[ni][0] += BDw[gb0 - cb];
                    S[ni][1] += BDw[gb0 - cb - 1];
                    S[ni][2] += BDw[gb1 - cb];
                    S[ni][3] += BDw[gb1 - cb - 1];
                }
            }
            // ---- causal mask (near-diagonal warps only) ----
            if (jr + 63 > 16*w) {
                const int a_lo = m0, a_hi = m0 + 8;
#pragma unroll
                for (int ni = 0; ni < 8; ni++) {
                    int cj = ni*8 + 2*qc + jr;
                    if (cj     > a_lo) S[ni][0] = -1e30f;
                    if (cj + 1 > a_lo) S[ni][1] = -1e30f;
                    if (cj     > a_hi) S[ni][2] = -1e30f;
                    if (cj + 1 > a_hi) S[ni][3] = -1e30f;
                }
            }
            // ---- online softmax (rows owned by quads) ----
            float rm0 = -1e30f, rm1 = -1e30f;
#pragma unroll
            for (int ni = 0; ni < 8; ni++) {
                rm0 = fmaxf(rm0, fmaxf(S[ni][0], S[ni][1]));
                rm1 = fmaxf(rm1, fmaxf(S[ni][2], S[ni][3]));
            }
#pragma unroll
            for (int msk = 1; msk < 4; msk <<= 1) {
                rm0 = fmaxf(rm0, __shfl_xor_sync(0xffffffffu, rm0, msk));
                rm1 = fmaxf(rm1, __shfl_xor_sync(0xffffffffu, rm1, msk));
            }
            float mn0 = fmaxf(mx0, rm0), mn1 = fmaxf(mx1, rm1);
            float cr0 = __expf(mx0 - mn0), cr1 = __expf(mx1 - mn1);
            mx0 = mn0; mx1 = mn1;
            float rs0 = 0.f, rs1 = 0.f;
#pragma unroll
            for (int ni = 0; ni < 8; ni++) {
                S[ni][0] = __expf(S[ni][0] - mn0); rs0 += S[ni][0];
                S[ni][1] = __expf(S[ni][1] - mn0); rs0 += S[ni][1];
                S[ni][2] = __expf(S[ni][2] - mn1); rs1 += S[ni][2];
                S[ni][3] = __expf(S[ni][3] - mn1); rs1 += S[ni][3];
            }
#pragma unroll
            for (int msk = 1; msk < 4; msk <<= 1) {
                rs0 += __shfl_xor_sync(0xffffffffu, rs0, msk);
                rs1 += __shfl_xor_sync(0xffffffffu, rs1, msk);
            }
            l0 = l0*cr0 + rs0;
            l1 = l1*cr1 + rs1;
#pragma unroll
            for (int ni = 0; ni < 8; ni++) {
                O[ni][0] *= cr0; O[ni][1] *= cr0;
                O[ni][2] *= cr1; O[ni][3] *= cr1;
            }
            // ---- O += P @ V  (P = S fragments, straight from registers) ----
#pragma unroll
            for (int k8 = 0; k8 < 8; k8++)
#pragma unroll
                for (int ni = 0; ni < 8; ni++) {
                    float2 bv = *(const float2*)&Vb[(ni*8+qr)*KS + k8*8 + 2*qc];
                    mma8(O[ni][0],O[ni][1],O[ni][2],O[ni][3],
                         FU(S[k8][0]),FU(S[k8][2]),FU(S[k8][1]),FU(S[k8][3]),
                         FU(bv.x),FU(bv.y));
                }
        }
        __syncthreads();                  // all warps done with this buffer
    }

    // ---- epilogue: normalize + write [b][l][n*64+d] ----
    float inv0 = 1.f/l0, inv1 = 1.f/l1;
    size_t o0 = ((size_t)(b*CL + i0 + m0))*CH + n*CD;
    size_t o1 = o0 + 8*CH;
#pragma unroll
    for (int ni = 0; ni < 8; ni++) {
        int d = ni*8 + 2*qc;
        *(float2*)&g_att[o0 + d] = make_float2(O[ni][0]*inv0, O[ni][1]*inv0);
        *(float2*)&g_att[o1 + d] = make_float2(O[ni][2]*inv1, O[ni][3]*inv1);
    }
}

// ---------------- layernorm(X + R) --------------------------------------
__global__ void __launch_bounds__(256) ln_kernel(const float* __restrict__ X,
    const float* __restrict__ R, const float* __restrict__ w,
    const float* __restrict__ bb, float* __restrict__ out)
{
    __shared__ float sh[8];
    int row = blockIdx.x, t = threadIdx.x;
    const float* xp = X + (size_t)row*CH;
    const float* rp = R + (size_t)row*CH;
    float v0 = xp[t] + rp[t];
    float v1 = xp[t+256] + rp[t+256];

    float s = v0 + v1;
#pragma unroll
    for (int m=16;m;m>>=1) s += __shfl_xor_sync(0xffffffffu, s, m);
    if ((t & 31)==0) sh[t>>5] = s;
    __syncthreads();
    float tot = 0.f;
#pragma unroll
    for (int i=0;i<8;i++) tot += sh[i];
    __syncthreads();
    float mean = tot * (1.0f/CH);
    float d0 = v0 - mean, d1 = v1 - mean;
    float s2 = d0*d0 + d1*d1;
#pragma unroll
    for (int m=16;m;m>>=1) s2 += __shfl_xor_sync(0xffffffffu, s2, m);
    if ((t & 31)==0) sh[t>>5] = s2;
    __syncthreads();
    float tot2 = 0.f;
#pragma unroll
    for (int i=0;i<8;i++) tot2 += sh[i];
    float rstd = rsqrtf(tot2*(1.0f/CH) + 1e-12f);
    out[(size_t)row*CH + t]       = w[t]*d0*rstd + bb[t];
    out[(size_t)row*CH + t + 256] = w[t+256]*d1*rstd + bb[t+256];
}

// ---------------- launch ----------------------------------------------------
extern "C" void kernel_launch(void* const* d_in, const int* in_sizes, int n_in,
                              void* d_out, int out_size)
{
    const float* x   = (const float*)d_in[0];
    const float* pe  = (const float*)d_in[1];
    const float* Wq  = (const float*)d_in[2];
    const float* bq  = (const float*)d_in[3];
    const float* Wk  = (const float*)d_in[4];
    const float* bk  = (const float*)d_in[5];
    const float* Wv  = (const float*)d_in[6];
    const float* bv  = (const float*)d_in[7];
    const float* Wr  = (const float*)d_in[8];
    const float* br  = (const float*)d_in[9];
    const float* cbv = (const float*)d_in[10];
    const float* pbv = (const float*)d_in[11];
    const float* Wc  = (const float*)d_in[12];
    const float* bc  = (const float*)d_in[13];
    const float* W1  = (const float*)d_in[14];
    const float* b1  = (const float*)d_in[15];
    const float* W2  = (const float*)d_in[16];
    const float* b2  = (const float*)d_in[17];
    const float* lnw = (const float*)d_in[18];
    const float* lnb = (const float*)d_in[19];
    float* out = (float*)d_out;

    float *pWqkv, *pWrP, *pAtt, *pT1, *pA, *pH1, *pT2;
    cudaGetSymbolAddress((void**)&pWqkv, g_Wqkv);
    cudaGetSymbolAddress((void**)&pWrP,  g_WrP);
    cudaGetSymbolAddress((void**)&pAtt,  g_att);
    cudaGetSymbolAddress((void**)&pT1,   g_t1);
    cudaGetSymbolAddress((void**)&pA,    g_a);
    cudaGetSymbolAddress((void**)&pH1,   g_h1);
    cudaGetSymbolAddress((void**)&pT2,   g_t2);

    cudaFuncSetAttribute(attn_mma,
        cudaFuncAttributeMaxDynamicSharedMemorySize, ATT_SMEM_BYTES);
    cudaFuncSetAttribute(tgemm<0>,
        cudaFuncAttributeMaxDynamicSharedMemorySize, TG_SMEM_BYTES);
    cudaFuncSetAttribute(tgemm<1>,
        cudaFuncAttributeMaxDynamicSharedMemorySize, TG_SMEM_BYTES);
    cudaFuncSetAttribute(tgemm<2>,
        cudaFuncAttributeMaxDynamicSharedMemorySize, TG_SMEM_BYTES);
    cudaFuncSetAttribute(tgemm<3>,
        cudaFuncAttributeMaxDynamicSharedMemorySize, TG_SMEM_BYTES);

    pack_kernel<<<128, 256>>>(Wq, Wk, Wv, Wr);

    // QKV: [8192,512] x [512,1536]  (B^T rows = 1536)
    tgemm<0><<<dim3(1536/128, CBL/128), 256, TG_SMEM_BYTES>>>(x, pWqkv, CBL, 1536, CH,
                                              bq, bk, bv, cbv, nullptr);
    // R: [2048,512] x [512,512]
    tgemm<1><<<dim3(CH/128, CL/128), 256, TG_SMEM_BYTES>>>(pe, pWrP, CL, CH, CH,
                                           br, nullptr, nullptr, nullptr, nullptr);
    // attention: 128-row Q tiles
    attn_mma<<<dim3(CL/128, CN, CB), 256, ATT_SMEM_BYTES>>>(cbv, pbv);

    // out @ Wc^T + bc -> t1   (B^T = Wc row-major directly)
    tgemm<2><<<dim3(CH/128, CBL/128), 256, TG_SMEM_BYTES>>>(pAtt, Wc, CBL, CH, CH,
                                            bc, nullptr, nullptr, nullptr, pT1);
    // a = LN(t1 + x)
    ln_kernel<<<CBL, 256>>>(pT1, x, lnw, lnb, pA);
    // h1 = gelu(a @ W1^T + b1)
    tgemm<3><<<dim3(CH/128, CBL/128), 256, TG_SMEM_BYTES>>>(pA, W1, CBL, CH, CH,
                                            b1, nullptr, nullptr, nullptr, pH1);
    // t2 = h1 @ W2^T + b2
    tgemm<2><<<dim3(CH/128, CBL/128), 256, TG_SMEM_BYTES>>>(pH1, W2, CBL, CH, CH,
                                            b2, nullptr, nullptr, nullptr, pT2);
    // out = LN(t2 + a)
    ln_kernel<<<CBL, 256>>>(pT2, pA, lnw, lnb, out);
}